// round 14
// baseline (speedup 1.0000x reference)
#include <cuda_runtime.h>
#include <math.h>

// ---------------- problem constants ----------------
#define BB   4
#define NN   50000
#define EE   1600000
#define DD   64
#define R2C  1000
#define TT   32
#define MM   10000
#define LL   3
#define KK   5000        // nodes kept per layer
#define ESELC 160000     // edges kept per layer
#define NBINS 65536      // 16-bit radix digits

typedef unsigned long long u64;
typedef unsigned int u32;

static inline int cdiv(long long a, long long b) { return (int)((a + b - 1) / b); }

// ---------------- device scratch (no allocation allowed) ----------------
__device__ float g_hidden[(size_t)BB * NN * DD];
__device__ float g_sumA [(size_t)BB * NN * DD];
__device__ float g_sqA  [(size_t)BB * NN * DD];
__device__ float g_mxA  [(size_t)BB * NN * DD];
__device__ float g_mnA  [(size_t)BB * NN * DD];
__device__ float g_score[BB * NN];
__device__ float g_deg  [BB * NN];
__device__ unsigned char g_sel[BB * NN];
__device__ float g_relpart[BB * DD];
__device__ float g_degfull[NN];
__device__ int   g_owner[NN];
__device__ float g_dmean_sum;
__device__ float g_dmean;
__device__ float g_base;
__device__ u64   g_keyA[(size_t)BB * EE];
__device__ u64   g_keyB[(size_t)BB * EE];
__device__ int   g_cntA[BB];
__device__ int   g_cntB[BB];
__device__ u64   g_thresh[BB];
__device__ int   g_kth[BB];
__device__ u32   g_hist[BB * NBINS];
__device__ int   g_seledge[BB * ESELC];
__device__ int   g_nsel[BB];

// ---------------- helpers ----------------
__device__ __forceinline__ u32 ford(float f) {
    u32 u = __float_as_uint(f);
    return (u & 0x80000000u) ? ~u : (u | 0x80000000u);  // order-preserving float->uint
}
// Float atomic max/min via signed-max (non-negative) / unsigned-min (negative)
// paths. Zeros MUST be canonicalized: -0.0 through the signed path has bit
// pattern INT_MIN and loses to everything (left mx at -inf -> NaN cascade).
__device__ __forceinline__ void atomicMaxF(float* a, float v) {
    u32 bv = __float_as_uint(v);
    if (bv == 0x80000000u) bv = 0u;            // -0 -> +0
    if (!(bv & 0x80000000u)) atomicMax((int*)a, (int)bv);
    else                     atomicMin((u32*)a, bv);
}
__device__ __forceinline__ void atomicMinF(float* a, float v) {
    u32 bv = __float_as_uint(v);
    if (bv == 0u) bv = 0x80000000u;            // +0 -> -0
    if (!(bv & 0x80000000u)) atomicMin((int*)a, (int)bv);
    else                     atomicMax((u32*)a, bv);
}

// ---------------- setup kernels ----------------
__global__ void k_init0() {
    size_t i = (size_t)blockIdx.x * blockDim.x + threadIdx.x;
    if (i < (size_t)BB * NN * DD) g_hidden[i] = 0.f;
    if (i < NN) { g_degfull[i] = 0.f; g_owner[i] = -1; }
    if (i == 0) g_dmean_sum = 0.f;
}

__global__ void k_degfull(const int* __restrict__ esrc) {
    int e = blockIdx.x * blockDim.x + threadIdx.x;
    if (e < EE) atomicAdd(&g_degfull[esrc[e]], 1.f);
}

__global__ void k_dmean() {
    __shared__ float s[256];
    int i = blockIdx.x * 256 + threadIdx.x;
    float v = 0.f;
    if (i < NN) v = logf(g_degfull[i] + 1.f);
    s[threadIdx.x] = v;
    __syncthreads();
    for (int o = 128; o > 0; o >>= 1) {
        if (threadIdx.x < o) s[threadIdx.x] += s[threadIdx.x + o];
        __syncthreads();
    }
    if (threadIdx.x == 0) atomicAdd(&g_dmean_sum, s[0]);
}
__global__ void k_dmean_fin() { g_dmean = g_dmean_sum / (float)NN; }

// last-occurrence-wins ownership for duplicate scatter indices (XLA CPU semantics)
__global__ void k_owner(const int* __restrict__ all_index) {
    int m = blockIdx.x * blockDim.x + threadIdx.x;
    if (m < MM) atomicMax(&g_owner[all_index[m]], m);
}
__global__ void k_scatter(const int* __restrict__ all_index, const float* __restrict__ embs) {
    int id = blockIdx.x * blockDim.x + threadIdx.x;
    if (id >= MM * DD) return;
    int m = id / DD, j = id % DD;
    int idx = all_index[m];
    if (g_owner[idx] != m) return;
    float v = embs[(size_t)m * DD + j];
    for (int b = 0; b < BB; b++)
        g_hidden[((size_t)b * NN + idx) * DD + j] = v;
}
__global__ void k_sethead(const int* __restrict__ h_index, const float* __restrict__ hs) {
    int id = threadIdx.x;  // BB*DD = 256 threads
    int b = id / DD, j = id % DD;
    int h = h_index[b];
    g_hidden[((size_t)b * NN + h) * DD + j] = hs[b * DD + j];
}

// rel_part[b] = rel @ W_bottom + linear_b
__global__ void k_relpart(const int* __restrict__ r_index, const float* __restrict__ rel_table,
                          const float* __restrict__ linear_w, const float* __restrict__ linear_b) {
    int b = blockIdx.x, j = threadIdx.x;  // 64 threads
    const float* rel = rel_table + (size_t)r_index[b] * DD;
    float acc = linear_b[j];
    for (int k = 0; k < DD; k++) acc += rel[k] * linear_w[(DD + k) * DD + j];
    g_relpart[b * DD + j] = acc;
}

// base = score_fn(0) = relu(b1) @ w2 + b2 (rel-independent)
__global__ void k_base(const float* __restrict__ mlp_b1, const float* __restrict__ mlp_w2,
                       const float* __restrict__ mlp_b2) {
    __shared__ float s[128];
    int t = threadIdx.x;
    s[t] = fmaxf(mlp_b1[t], 0.f) * mlp_w2[t];
    __syncthreads();
    for (int o = 64; o > 0; o >>= 1) {
        if (t < o) s[t] += s[t + o];
        __syncthreads();
    }
    if (t == 0) g_base = s[0] + mlp_b2[0];
}
__global__ void k_scorefill() {
    int i = blockIdx.x * blockDim.x + threadIdx.x;
    if (i < BB * NN) g_score[i] = g_base;
}

// score_fn: head_mode=1 scores the head node unconditionally; else nodes with deg>0
__global__ void __launch_bounds__(128) k_score(
        int head_mode, const int* __restrict__ h_index,
        const float* __restrict__ linear_w,
        const float* __restrict__ mlp_w1, const float* __restrict__ mlp_b1,
        const float* __restrict__ mlp_w2, const float* __restrict__ mlp_b2) {
    int b = blockIdx.y;
    int n;
    if (head_mode) n = h_index[b];
    else {
        n = blockIdx.x;
        if (g_deg[b * NN + n] <= 0.f) return;  // block-uniform
    }
    int t = threadIdx.x;  // 128
    __shared__ float sh[DD], sx[DD], sr[128];
    if (t < DD) sh[t] = g_hidden[((size_t)b * NN + n) * DD + t];
    __syncthreads();
    if (t < DD) {
        float acc = g_relpart[b * DD + t];
        #pragma unroll 8
        for (int k = 0; k < DD; k++) acc += sh[k] * linear_w[k * DD + t];
        sx[t] = sh[t] * acc;
    }
    __syncthreads();
    float h1 = mlp_b1[t];
    #pragma unroll 8
    for (int j = 0; j < DD; j++) h1 += sx[j] * mlp_w1[j * 128 + t];
    h1 = fmaxf(h1, 0.f);
    sr[t] = h1 * mlp_w2[t];
    __syncthreads();
    for (int o = 64; o > 0; o >>= 1) {
        if (t < o) sr[t] += sr[t + o];
        __syncthreads();
    }
    if (t == 0) g_score[b * NN + n] = sr[0] + mlp_b2[0];
}

// ---------------- radix-select machinery (16-bit digits, 4 passes) ----------------
__global__ void k_selinit_nodes() {
    int b = threadIdx.x;
    if (b < BB) { g_cntA[b] = NN; g_kth[b] = KK; g_thresh[b] = 0ull; }
}
__global__ void k_selinit_edges() {
    int b = threadIdx.x;
    if (b < BB) { g_cntA[b] = 0; g_thresh[b] = 0ull; g_nsel[b] = 0; }
}
__global__ void k_clampkth() {
    int b = threadIdx.x;
    if (b < BB) g_kth[b] = min(ESELC, g_cntA[b]);
}
__global__ void k_nkeys() {
    int b = blockIdx.y;
    int n = blockIdx.x * blockDim.x + threadIdx.x;
    if (n >= NN) return;
    u64 key = ((u64)ford(g_score[b * NN + n]) << 32) | (u32)(0x7FFFFFFF - n);
    g_keyA[(size_t)b * EE + n] = key;
}
__global__ void k_ekeys(const int* __restrict__ esrc, const int* __restrict__ edst) {
    int b = blockIdx.y;
    int e = blockIdx.x * blockDim.x + threadIdx.x;
    if (e >= EE) return;
    if (!g_sel[b * NN + esrc[e]]) return;
    u64 key = ((u64)ford(g_score[b * NN + edst[e]]) << 32) | (u32)(0x7FFFFFFF - e);
    int p = atomicAdd(&g_cntA[b], 1);
    g_keyA[(size_t)b * EE + p] = key;
}
__global__ void k_zerohist() {
    int i = blockIdx.x * blockDim.x + threadIdx.x;
    if (i < BB * NBINS) g_hist[i] = 0u;
}
__global__ void k_hist(int srcIsA, int shift) {
    int b = blockIdx.y;
    int idx = blockIdx.x * blockDim.x + threadIdx.x;
    int cnt = srcIsA ? g_cntA[b] : g_cntB[b];
    if (idx >= cnt) return;
    const u64* s = srcIsA ? g_keyA : g_keyB;
    u32 bucket = (u32)((s[(size_t)b * EE + idx] >> shift) & 0xFFFFull);
    atomicAdd(&g_hist[b * NBINS + bucket], 1u);
}
// find the bucket (descending) containing the k-th largest; update prefix & k
__global__ void __launch_bounds__(1024) k_pick(int shift, int srcIsA) {
    int b = blockIdx.x;
    int t = threadIdx.x;  // 1024
    const u32* h = &g_hist[b * NBINS];
    int hi = 65535 - t * 64;
    int partial = 0;
    #pragma unroll
    for (int i = 0; i < 64; i++) partial += (int)h[hi - i];
    __shared__ int sp[1024];
    sp[t] = partial;
    __syncthreads();
    for (int off = 1; off < 1024; off <<= 1) {
        int v = (t >= off) ? sp[t - off] : 0;
        __syncthreads();
        sp[t] += v;
        __syncthreads();
    }
    int incl = sp[t];
    int excl = incl - partial;
    int k = g_kth[b];
    if (k >= 1 && excl < k && incl >= k) {
        int cum = excl;
        for (int i = 0; i < 64; i++) {
            int c = (int)h[hi - i];
            cum += c;
            if (cum >= k) {
                g_thresh[b] |= ((u64)(u32)(hi - i)) << shift;
                g_kth[b] = k - (cum - c);
                break;
            }
        }
    }
    if (t == 0) {  // zero the destination counter for the following compact
        if (srcIsA) g_cntB[b] = 0; else g_cntA[b] = 0;
    }
}
__global__ void k_compact(int srcIsA, int shift) {
    int b = blockIdx.y;
    int idx = blockIdx.x * blockDim.x + threadIdx.x;
    int cnt = srcIsA ? g_cntA[b] : g_cntB[b];
    if (idx >= cnt) return;
    const u64* s = srcIsA ? g_keyA : g_keyB;
    u64* d = srcIsA ? g_keyB : g_keyA;
    u64 key = s[(size_t)b * EE + idx];
    if (((key >> shift) & 0xFFFFull) == ((g_thresh[b] >> shift) & 0xFFFFull)) {
        int p = atomicAdd(srcIsA ? &g_cntB[b] : &g_cntA[b], 1);
        d[(size_t)b * EE + p] = key;
    }
}
__global__ void k_marksel() {
    int b = blockIdx.y;
    int n = blockIdx.x * blockDim.x + threadIdx.x;
    if (n >= NN) return;
    u64 key = ((u64)ford(g_score[b * NN + n]) << 32) | (u32)(0x7FFFFFFF - n);
    g_sel[b * NN + n] = (key >= g_thresh[b]) ? 1 : 0;
}
__global__ void k_markedges(const int* __restrict__ esrc, const int* __restrict__ edst) {
    int b = blockIdx.y;
    int e = blockIdx.x * blockDim.x + threadIdx.x;
    if (e >= EE) return;
    if (!g_sel[b * NN + esrc[e]]) return;
    u64 key = ((u64)ford(g_score[b * NN + edst[e]]) << 32) | (u32)(0x7FFFFFFF - e);
    if (key >= g_thresh[b]) {
        int p = atomicAdd(&g_nsel[b], 1);
        if (p < ESELC) g_seledge[b * ESELC + p] = e;
    }
}

// ---------------- aggregation + PNA ----------------
__global__ void k_aggfill() {
    size_t i = (size_t)blockIdx.x * blockDim.x + threadIdx.x;
    if (i < (size_t)BB * NN * DD) {
        g_sumA[i] = 0.f; g_sqA[i] = 0.f;
        g_mxA[i] = -INFINITY; g_mnA[i] = INFINITY;
    }
    if (i < (size_t)BB * NN) g_deg[i] = 0.f;
}

// one edge per 64 threads (2 warps); block = 4 edges
__global__ void __launch_bounds__(256) k_msg(
        const int* __restrict__ esrc, const int* __restrict__ edst,
        const int* __restrict__ etyp, const float* __restrict__ relw_l) {
    int b = blockIdx.y;
    int i = blockIdx.x * 4 + (threadIdx.x >> 6);
    int j = threadIdx.x & 63;
    if (i >= g_nsel[b]) return;
    // lane 0 of each 32-lane group reads edge metadata once, broadcast via shfl
    int e = 0, s = 0, d = 0, t = 0;
    if ((threadIdx.x & 31) == 0) {
        e = g_seledge[b * ESELC + i];
        s = esrc[e]; d = edst[e]; t = etyp[e];
    }
    s = __shfl_sync(0xFFFFFFFFu, s, 0);
    d = __shfl_sync(0xFFFFFFFFu, d, 0);
    t = __shfl_sync(0xFFFFFFFFu, t, 0);
    float gate = 1.f / (1.f + expf(-g_score[b * NN + s]));
    float m = gate * g_hidden[((size_t)b * NN + s) * DD + j] * relw_l[(size_t)t * DD + j];
    size_t o = ((size_t)b * NN + d) * DD + j;
    atomicAdd(&g_sumA[o], m);
    atomicAdd(&g_sqA[o], m * m);
    atomicMaxF(&g_mxA[o], m);
    atomicMinF(&g_mnA[o], m);
    if (j == 0) atomicAdd(&g_deg[b * NN + d], 1.f);
}

// per active node: build feats[768], out = feats @ W + b, hidden += out
__global__ void __launch_bounds__(64) k_pna(const float* __restrict__ pw,
                                            const float* __restrict__ pb) {
    int b = blockIdx.y, n = blockIdx.x, j = threadIdx.x;  // 64 threads
    float deg = g_deg[b * NN + n];
    if (deg <= 0.f) return;  // block-uniform
    __shared__ float sf[12 * DD];
    size_t o = ((size_t)b * NN + n) * DD + j;
    float degc = fmaxf(deg, 1.f);
    float sm = g_sumA[o], sq = g_sqA[o], mx = g_mxA[o], mn = g_mnA[o];
    // defensive: an untouched extremum on an active node corresponds to an
    // all-zero message segment -> reference value is 0
    if (isinf(mx)) mx = 0.f;
    if (isinf(mn)) mn = 0.f;
    float mean = sm / degc;
    float var  = sq / degc - mean * mean;
    float stdv = sqrtf(fmaxf(var, 0.f) + 1e-6f);
    float logd = logf(deg + 1.f);
    float dm = g_dmean;
    float amp = logd / dm;
    float att = dm / fmaxf(logd, 1e-6f);
    sf[0 * DD + j] = mean;        sf[1 * DD + j] = mean * amp;  sf[2 * DD + j] = mean * att;
    sf[3 * DD + j] = mx;          sf[4 * DD + j] = mx * amp;    sf[5 * DD + j] = mx * att;
    sf[6 * DD + j] = mn;          sf[7 * DD + j] = mn * amp;    sf[8 * DD + j] = mn * att;
    sf[9 * DD + j] = stdv;        sf[10 * DD + j] = stdv * amp; sf[11 * DD + j] = stdv * att;
    __syncthreads();
    float acc = pb[j];
    #pragma unroll 8
    for (int f = 0; f < 12 * DD; f++) acc += sf[f] * pw[(size_t)f * DD + j];
    g_hidden[o] += acc;
}

__global__ void k_out(const int* __restrict__ t_index, float* __restrict__ out) {
    int i = blockIdx.x * blockDim.x + threadIdx.x;
    if (i >= BB * TT) return;
    int b = i / TT;
    out[i] = g_score[(size_t)b * NN + t_index[i]];
}

// ---------------- launch sequence ----------------
extern "C" void kernel_launch(void* const* d_in, const int* in_sizes, int n_in,
                              void* d_out, int out_size) {
    const int*   h_index         = (const int*)d_in[0];
    const int*   r_index         = (const int*)d_in[1];
    const int*   t_index         = (const int*)d_in[2];
    const int*   all_index       = (const int*)d_in[3];
    const int*   edge_src        = (const int*)d_in[4];
    const int*   edge_dst        = (const int*)d_in[5];
    const int*   edge_type       = (const int*)d_in[6];
    const float* hidden_states   = (const float*)d_in[7];
    const float* score_text_embs = (const float*)d_in[8];
    const float* rel_table       = (const float*)d_in[9];
    const float* linear_w        = (const float*)d_in[10];
    const float* linear_b        = (const float*)d_in[11];
    const float* mlp_w1          = (const float*)d_in[12];
    const float* mlp_b1          = (const float*)d_in[13];
    const float* mlp_w2          = (const float*)d_in[14];
    const float* mlp_b2          = (const float*)d_in[15];
    const float* relw            = (const float*)d_in[16];
    const float* pna_w           = (const float*)d_in[17];
    const float* pna_b           = (const float*)d_in[18];
    float* out = (float*)d_out;
    (void)in_sizes; (void)n_in; (void)out_size;

    // ---- setup ----
    k_init0<<<cdiv((long long)BB * NN * DD, 256), 256>>>();
    k_degfull<<<cdiv(EE, 256), 256>>>(edge_src);
    k_dmean<<<cdiv(NN, 256), 256>>>();
    k_dmean_fin<<<1, 1>>>();
    k_owner<<<cdiv(MM, 256), 256>>>(all_index);
    k_scatter<<<cdiv((long long)MM * DD, 256), 256>>>(all_index, score_text_embs);
    k_sethead<<<1, BB * DD>>>(h_index, hidden_states);
    k_relpart<<<BB, DD>>>(r_index, rel_table, linear_w, linear_b);
    k_base<<<1, 128>>>(mlp_b1, mlp_w2, mlp_b2);
    k_scorefill<<<cdiv(BB * NN, 256), 256>>>();
    k_score<<<dim3(1, BB), 128>>>(1, h_index, linear_w, mlp_w1, mlp_b1, mlp_w2, mlp_b2);

    for (int l = 0; l < LL; l++) {
        const float* relw_l = relw + (size_t)l * R2C * DD;
        const float* pw     = pna_w + (size_t)l * 12 * DD * DD;
        const float* pb     = pna_b + (size_t)l * DD;

        // ---- node top-K (exact, tie-break lower index) ----
        k_selinit_nodes<<<1, 32>>>();
        k_nkeys<<<dim3(cdiv(NN, 256), BB), 256>>>();
        for (int p = 0; p < 4; p++) {
            int shift = 48 - 16 * p;
            int srcA = ((p & 1) == 0) ? 1 : 0;
            k_zerohist<<<cdiv(BB * NBINS, 256), 256>>>();
            k_hist<<<dim3(cdiv(NN, 256), BB), 256>>>(srcA, shift);
            k_pick<<<BB, 1024>>>(shift, srcA);
            if (p < 3) k_compact<<<dim3(cdiv(NN, 256), BB), 256>>>(srcA, shift);
        }
        k_marksel<<<dim3(cdiv(NN, 256), BB), 256>>>();

        // ---- edge top-ESEL among finite (sel-src) edges ----
        k_selinit_edges<<<1, 32>>>();
        k_ekeys<<<dim3(cdiv(EE, 256), BB), 256>>>(edge_src, edge_dst);
        k_clampkth<<<1, 32>>>();
        for (int p = 0; p < 4; p++) {
            int shift = 48 - 16 * p;
            int srcA = ((p & 1) == 0) ? 1 : 0;
            k_zerohist<<<cdiv(BB * NBINS, 256), 256>>>();
            k_hist<<<dim3(cdiv(EE, 256), BB), 256>>>(srcA, shift);
            k_pick<<<BB, 1024>>>(shift, srcA);
            if (p < 3) k_compact<<<dim3(cdiv(EE, 256), BB), 256>>>(srcA, shift);
        }
        k_markedges<<<dim3(cdiv(EE, 256), BB), 256>>>(edge_src, edge_dst);

        // ---- aggregate + PNA update + rescore ----
        k_aggfill<<<cdiv((long long)BB * NN * DD, 256), 256>>>();
        k_msg<<<dim3(cdiv(ESELC, 4), BB), 256>>>(edge_src, edge_dst, edge_type, relw_l);
        k_pna<<<dim3(NN, BB), DD>>>(pw, pb);
        k_score<<<dim3(NN, BB), 128>>>(0, h_index, linear_w, mlp_w1, mlp_b1, mlp_w2, mlp_b2);
    }

    k_out<<<cdiv(BB * TT, 128), 128>>>(t_index, out);
}

// round 15
// speedup vs baseline: 1.2676x; 1.2676x over previous
#include <cuda_runtime.h>
#include <math.h>

// ---------------- problem constants ----------------
#define BB   4
#define NN   50000
#define EE   1600000
#define DD   64
#define R2C  1000
#define TT   32
#define MM   10000
#define LL   3
#define KK   5000        // nodes kept per layer
#define ESELC 160000     // edges kept per layer
#define NBINS 65536      // 16-bit radix digits

typedef unsigned long long u64;
typedef unsigned int u32;

static inline int cdiv(long long a, long long b) { return (int)((a + b - 1) / b); }

// ---------------- device scratch (no allocation allowed) ----------------
__device__ float g_hidden[(size_t)BB * NN * DD];
__device__ float g_sumA [(size_t)BB * NN * DD];   // after k_prep: mean
__device__ float g_sqA  [(size_t)BB * NN * DD];   // after k_prep: std
__device__ float g_mxA  [(size_t)BB * NN * DD];   // after k_prep: mx (inf->0)
__device__ float g_mnA  [(size_t)BB * NN * DD];   // after k_prep: mn (inf->0)
__device__ float g_score[BB * NN];
__device__ float g_deg  [BB * NN];
__device__ unsigned char g_sel[BB * NN];
__device__ float g_relpart[BB * DD];
__device__ float g_degfull[NN];
__device__ int   g_owner[NN];
__device__ float g_dmean_sum;
__device__ float g_dmean;
__device__ float g_base;
__device__ u64   g_keyA[(size_t)BB * EE];
__device__ u64   g_keyB[(size_t)BB * EE];
__device__ int   g_cntA[BB];
__device__ int   g_cntB[BB];
__device__ u64   g_thresh[BB];
__device__ int   g_kth[BB];
__device__ u32   g_hist[BB * NBINS];
__device__ int   g_seledge[BB * ESELC];
__device__ int   g_nsel[BB];
// active-node machinery
__device__ int   g_act[BB * NN];
__device__ float g_amp[BB * NN];
__device__ float g_att[BB * NN];
__device__ int   g_nact;

// ---------------- helpers ----------------
__device__ __forceinline__ u32 ford(float f) {
    u32 u = __float_as_uint(f);
    return (u & 0x80000000u) ? ~u : (u | 0x80000000u);  // order-preserving float->uint
}
// Float atomic max/min; zeros canonicalized (-0 loses as INT_MIN otherwise).
__device__ __forceinline__ void atomicMaxF(float* a, float v) {
    u32 bv = __float_as_uint(v);
    if (bv == 0x80000000u) bv = 0u;            // -0 -> +0
    if (!(bv & 0x80000000u)) atomicMax((int*)a, (int)bv);
    else                     atomicMin((u32*)a, bv);
}
__device__ __forceinline__ void atomicMinF(float* a, float v) {
    u32 bv = __float_as_uint(v);
    if (bv == 0u) bv = 0x80000000u;            // +0 -> -0
    if (!(bv & 0x80000000u)) atomicMin((int*)a, (int)bv);
    else                     atomicMax((u32*)a, bv);
}

// ---------------- setup kernels ----------------
__global__ void k_init0() {
    size_t i = (size_t)blockIdx.x * blockDim.x + threadIdx.x;
    if (i < (size_t)BB * NN * DD) g_hidden[i] = 0.f;
    if (i < NN) { g_degfull[i] = 0.f; g_owner[i] = -1; }
    if (i == 0) g_dmean_sum = 0.f;
}

__global__ void k_degfull(const int* __restrict__ esrc) {
    int e = blockIdx.x * blockDim.x + threadIdx.x;
    if (e < EE) atomicAdd(&g_degfull[esrc[e]], 1.f);
}

__global__ void k_dmean() {
    __shared__ float s[256];
    int i = blockIdx.x * 256 + threadIdx.x;
    float v = 0.f;
    if (i < NN) v = logf(g_degfull[i] + 1.f);
    s[threadIdx.x] = v;
    __syncthreads();
    for (int o = 128; o > 0; o >>= 1) {
        if (threadIdx.x < o) s[threadIdx.x] += s[threadIdx.x + o];
        __syncthreads();
    }
    if (threadIdx.x == 0) atomicAdd(&g_dmean_sum, s[0]);
}
__global__ void k_dmean_fin() { g_dmean = g_dmean_sum / (float)NN; }

// last-occurrence-wins ownership for duplicate scatter indices
__global__ void k_owner(const int* __restrict__ all_index) {
    int m = blockIdx.x * blockDim.x + threadIdx.x;
    if (m < MM) atomicMax(&g_owner[all_index[m]], m);
}
__global__ void k_scatter(const int* __restrict__ all_index, const float* __restrict__ embs) {
    int id = blockIdx.x * blockDim.x + threadIdx.x;
    if (id >= MM * DD) return;
    int m = id / DD, j = id % DD;
    int idx = all_index[m];
    if (g_owner[idx] != m) return;
    float v = embs[(size_t)m * DD + j];
    for (int b = 0; b < BB; b++)
        g_hidden[((size_t)b * NN + idx) * DD + j] = v;
}
__global__ void k_sethead(const int* __restrict__ h_index, const float* __restrict__ hs) {
    int id = threadIdx.x;  // BB*DD = 256 threads
    int b = id / DD, j = id % DD;
    int h = h_index[b];
    g_hidden[((size_t)b * NN + h) * DD + j] = hs[b * DD + j];
}

// rel_part[b] = rel @ W_bottom + linear_b
__global__ void k_relpart(const int* __restrict__ r_index, const float* __restrict__ rel_table,
                          const float* __restrict__ linear_w, const float* __restrict__ linear_b) {
    int b = blockIdx.x, j = threadIdx.x;  // 64 threads
    const float* rel = rel_table + (size_t)r_index[b] * DD;
    float acc = linear_b[j];
    for (int k = 0; k < DD; k++) acc += rel[k] * linear_w[(DD + k) * DD + j];
    g_relpart[b * DD + j] = acc;
}

// base = score_fn(0) = relu(b1) @ w2 + b2 (rel-independent)
__global__ void k_base(const float* __restrict__ mlp_b1, const float* __restrict__ mlp_w2,
                       const float* __restrict__ mlp_b2) {
    __shared__ float s[128];
    int t = threadIdx.x;
    s[t] = fmaxf(mlp_b1[t], 0.f) * mlp_w2[t];
    __syncthreads();
    for (int o = 64; o > 0; o >>= 1) {
        if (t < o) s[t] += s[t + o];
        __syncthreads();
    }
    if (t == 0) g_base = s[0] + mlp_b2[0];
}
__global__ void k_scorefill() {
    int i = blockIdx.x * blockDim.x + threadIdx.x;
    if (i < BB * NN) g_score[i] = g_base;
}

// initial head-only scoring (runs once; not perf-critical)
__global__ void __launch_bounds__(128) k_score_head(
        const int* __restrict__ h_index,
        const float* __restrict__ linear_w,
        const float* __restrict__ mlp_w1, const float* __restrict__ mlp_b1,
        const float* __restrict__ mlp_w2, const float* __restrict__ mlp_b2) {
    int b = blockIdx.y;
    int n = h_index[b];
    int t = threadIdx.x;  // 128
    __shared__ float sh[DD], sx[DD], sr[128];
    if (t < DD) sh[t] = g_hidden[((size_t)b * NN + n) * DD + t];
    __syncthreads();
    if (t < DD) {
        float acc = g_relpart[b * DD + t];
        #pragma unroll 8
        for (int k = 0; k < DD; k++) acc += sh[k] * linear_w[k * DD + t];
        sx[t] = sh[t] * acc;
    }
    __syncthreads();
    float h1 = mlp_b1[t];
    #pragma unroll 8
    for (int j = 0; j < DD; j++) h1 += sx[j] * mlp_w1[j * 128 + t];
    h1 = fmaxf(h1, 0.f);
    sr[t] = h1 * mlp_w2[t];
    __syncthreads();
    for (int o = 64; o > 0; o >>= 1) {
        if (t < o) sr[t] += sr[t + o];
        __syncthreads();
    }
    if (t == 0) g_score[b * NN + n] = sr[0] + mlp_b2[0];
}

// ---------------- radix-select machinery (16-bit digits, 4 passes) ----------------
__global__ void k_selinit_nodes() {
    int b = threadIdx.x;
    if (b < BB) { g_cntA[b] = NN; g_kth[b] = KK; g_thresh[b] = 0ull; }
}
__global__ void k_selinit_edges() {
    int b = threadIdx.x;
    if (b < BB) { g_cntA[b] = 0; g_thresh[b] = 0ull; g_nsel[b] = 0; }
}
__global__ void k_clampkth() {
    int b = threadIdx.x;
    if (b < BB) g_kth[b] = min(ESELC, g_cntA[b]);
}
__global__ void k_nkeys() {
    int b = blockIdx.y;
    int n = blockIdx.x * blockDim.x + threadIdx.x;
    if (n >= NN) return;
    u64 key = ((u64)ford(g_score[b * NN + n]) << 32) | (u32)(0x7FFFFFFF - n);
    g_keyA[(size_t)b * EE + n] = key;
}
__global__ void k_ekeys(const int* __restrict__ esrc, const int* __restrict__ edst) {
    int b = blockIdx.y;
    int e = blockIdx.x * blockDim.x + threadIdx.x;
    if (e >= EE) return;
    if (!g_sel[b * NN + esrc[e]]) return;
    u64 key = ((u64)ford(g_score[b * NN + edst[e]]) << 32) | (u32)(0x7FFFFFFF - e);
    int p = atomicAdd(&g_cntA[b], 1);
    g_keyA[(size_t)b * EE + p] = key;
}
__global__ void k_zerohist() {
    int i = blockIdx.x * blockDim.x + threadIdx.x;
    if (i < BB * NBINS) g_hist[i] = 0u;
}
__global__ void k_hist(int srcIsA, int shift) {
    int b = blockIdx.y;
    int idx = blockIdx.x * blockDim.x + threadIdx.x;
    int cnt = srcIsA ? g_cntA[b] : g_cntB[b];
    if (idx >= cnt) return;
    const u64* s = srcIsA ? g_keyA : g_keyB;
    u32 bucket = (u32)((s[(size_t)b * EE + idx] >> shift) & 0xFFFFull);
    atomicAdd(&g_hist[b * NBINS + bucket], 1u);
}
__global__ void __launch_bounds__(1024) k_pick(int shift, int srcIsA) {
    int b = blockIdx.x;
    int t = threadIdx.x;  // 1024
    const u32* h = &g_hist[b * NBINS];
    int hi = 65535 - t * 64;
    int partial = 0;
    #pragma unroll
    for (int i = 0; i < 64; i++) partial += (int)h[hi - i];
    __shared__ int sp[1024];
    sp[t] = partial;
    __syncthreads();
    for (int off = 1; off < 1024; off <<= 1) {
        int v = (t >= off) ? sp[t - off] : 0;
        __syncthreads();
        sp[t] += v;
        __syncthreads();
    }
    int incl = sp[t];
    int excl = incl - partial;
    int k = g_kth[b];
    if (k >= 1 && excl < k && incl >= k) {
        int cum = excl;
        for (int i = 0; i < 64; i++) {
            int c = (int)h[hi - i];
            cum += c;
            if (cum >= k) {
                g_thresh[b] |= ((u64)(u32)(hi - i)) << shift;
                g_kth[b] = k - (cum - c);
                break;
            }
        }
    }
    if (t == 0) {
        if (srcIsA) g_cntB[b] = 0; else g_cntA[b] = 0;
    }
}
__global__ void k_compact(int srcIsA, int shift) {
    int b = blockIdx.y;
    int idx = blockIdx.x * blockDim.x + threadIdx.x;
    int cnt = srcIsA ? g_cntA[b] : g_cntB[b];
    if (idx >= cnt) return;
    const u64* s = srcIsA ? g_keyA : g_keyB;
    u64* d = srcIsA ? g_keyB : g_keyA;
    u64 key = s[(size_t)b * EE + idx];
    if (((key >> shift) & 0xFFFFull) == ((g_thresh[b] >> shift) & 0xFFFFull)) {
        int p = atomicAdd(srcIsA ? &g_cntB[b] : &g_cntA[b], 1);
        d[(size_t)b * EE + p] = key;
    }
}
__global__ void k_marksel() {
    int b = blockIdx.y;
    int n = blockIdx.x * blockDim.x + threadIdx.x;
    if (n >= NN) return;
    u64 key = ((u64)ford(g_score[b * NN + n]) << 32) | (u32)(0x7FFFFFFF - n);
    g_sel[b * NN + n] = (key >= g_thresh[b]) ? 1 : 0;
}
__global__ void k_markedges(const int* __restrict__ esrc, const int* __restrict__ edst) {
    int b = blockIdx.y;
    int e = blockIdx.x * blockDim.x + threadIdx.x;
    if (e >= EE) return;
    if (!g_sel[b * NN + esrc[e]]) return;
    u64 key = ((u64)ford(g_score[b * NN + edst[e]]) << 32) | (u32)(0x7FFFFFFF - e);
    if (key >= g_thresh[b]) {
        int p = atomicAdd(&g_nsel[b], 1);
        if (p < ESELC) g_seledge[b * ESELC + p] = e;
    }
}

// ---------------- aggregation ----------------
__global__ void k_aggfill4() {
    size_t i = (size_t)blockIdx.x * blockDim.x + threadIdx.x;  // over BB*NN*DD/4
    const size_t NV = (size_t)BB * NN * DD / 4;
    if (i < NV) {
        float4 z = {0.f, 0.f, 0.f, 0.f};
        float4 ni = {-INFINITY, -INFINITY, -INFINITY, -INFINITY};
        float4 pi = {INFINITY, INFINITY, INFINITY, INFINITY};
        ((float4*)g_sumA)[i] = z;
        ((float4*)g_sqA)[i]  = z;
        ((float4*)g_mxA)[i]  = ni;
        ((float4*)g_mnA)[i]  = pi;
    }
    if (i < (size_t)BB * NN) g_deg[i] = 0.f;
    if (i == 0) g_nact = 0;
}

// one edge per 64 threads (2 warps); block = 4 edges
__global__ void __launch_bounds__(256) k_msg(
        const int* __restrict__ esrc, const int* __restrict__ edst,
        const int* __restrict__ etyp, const float* __restrict__ relw_l) {
    int b = blockIdx.y;
    int i = blockIdx.x * 4 + (threadIdx.x >> 6);
    int j = threadIdx.x & 63;
    if (i >= g_nsel[b]) return;
    int e = 0, s = 0, d = 0, t = 0;
    if ((threadIdx.x & 31) == 0) {
        e = g_seledge[b * ESELC + i];
        s = esrc[e]; d = edst[e]; t = etyp[e];
    }
    s = __shfl_sync(0xFFFFFFFFu, s, 0);
    d = __shfl_sync(0xFFFFFFFFu, d, 0);
    t = __shfl_sync(0xFFFFFFFFu, t, 0);
    float gate = 1.f / (1.f + expf(-g_score[b * NN + s]));
    float m = gate * g_hidden[((size_t)b * NN + s) * DD + j] * relw_l[(size_t)t * DD + j];
    size_t o = ((size_t)b * NN + d) * DD + j;
    atomicAdd(&g_sumA[o], m);
    atomicAdd(&g_sqA[o], m * m);
    atomicMaxF(&g_mxA[o], m);
    atomicMinF(&g_mnA[o], m);
    if (j == 0) atomicAdd(&g_deg[b * NN + d], 1.f);
}

// ---------------- PNA as batched GEMM over active nodes ----------------
// k_prep: convert raw aggregates in place to (mean, std, mx, mn); compute
// amp/att per node; compact active node indices into g_act.
__global__ void __launch_bounds__(64) k_prep() {
    int b = blockIdx.y, n = blockIdx.x, j = threadIdx.x;
    float deg = g_deg[b * NN + n];
    if (deg <= 0.f) return;  // block-uniform
    size_t o = ((size_t)b * NN + n) * DD + j;
    float degc = fmaxf(deg, 1.f);
    float sm = g_sumA[o], sq = g_sqA[o], mx = g_mxA[o], mn = g_mnA[o];
    if (isinf(mx)) mx = 0.f;
    if (isinf(mn)) mn = 0.f;
    float mean = sm / degc;
    float stdv = sqrtf(fmaxf(sq / degc - mean * mean, 0.f) + 1e-6f);
    g_sumA[o] = mean; g_sqA[o] = stdv; g_mxA[o] = mx; g_mnA[o] = mn;
    if (j == 0) {
        float logd = logf(deg + 1.f);
        float dm = g_dmean;
        int idx = b * NN + n;
        g_amp[idx] = logd / dm;
        g_att[idx] = dm / fmaxf(logd, 1e-6f);
        int p = atomicAdd(&g_nact, 1);
        g_act[p] = idx;
    }
}

// k_pnagemm: out[node][o] = sum_f feats[node][f] * pw[f][o] + pb[o];
// feats generated on-the-fly: f-block kc = agg*3+sc, A = base[agg][j]*scale[sc].
// 256 threads; 32 nodes per group; thread t: oq=t&15 (4 outs), np=t>>4 (nodes np, np+16).
__global__ void __launch_bounds__(256) k_pnagemm(const float* __restrict__ pw,
                                                 const float* __restrict__ pb) {
    __shared__ float spw[64 * 64];     // current pw chunk [j][o]
    __shared__ float sbase[32 * 64];   // current agg base [nd][j]
    __shared__ float sscale[32 * 3];
    __shared__ int   sidx[32];
    __shared__ float spb[64];
    int t = threadIdx.x;
    if (t < 64) spb[t] = pb[t];
    int nact = g_nact;
    int ngroups = (nact + 31) >> 5;
    int oq = t & 15;
    int np = t >> 4;
    float4* spw4 = (float4*)spw;
    for (int g = blockIdx.x; g < ngroups; g += gridDim.x) {
        __syncthreads();  // prev group done using sidx/sscale
        if (t < 32) {
            int i = g * 32 + t;
            int idx = (i < nact) ? g_act[i] : -1;
            sidx[t] = idx;
            if (idx >= 0) {
                sscale[t * 3 + 0] = 1.f;
                sscale[t * 3 + 1] = g_amp[idx];
                sscale[t * 3 + 2] = g_att[idx];
            } else {
                sscale[t * 3 + 0] = 0.f; sscale[t * 3 + 1] = 0.f; sscale[t * 3 + 2] = 0.f;
            }
        }
        __syncthreads();
        float4 acc0 = {0.f, 0.f, 0.f, 0.f};
        float4 acc1 = {0.f, 0.f, 0.f, 0.f};
        for (int agg = 0; agg < 4; agg++) {
            const float* src = (agg == 0) ? g_sumA : (agg == 1) ? g_mxA
                              : (agg == 2) ? g_mnA : g_sqA;
            __syncthreads();  // prev compute done reading sbase
            #pragma unroll
            for (int q = 0; q < 8; q++) {
                int id = q * 256 + t;      // 2048 = 32 nodes x 64 dims
                int nd = id >> 6, jj = id & 63;
                int idx = sidx[nd];
                sbase[id] = (idx >= 0) ? src[(size_t)idx * 64 + jj] : 0.f;
            }
            for (int sc = 0; sc < 3; sc++) {
                int kc = agg * 3 + sc;
                __syncthreads();  // prev compute done reading spw (also covers sbase fill)
                const float4* pws = (const float4*)(pw + (size_t)kc * 4096);
                #pragma unroll
                for (int q = 0; q < 4; q++) spw4[q * 256 + t] = pws[q * 256 + t];
                __syncthreads();
                float scA = sscale[np * 3 + sc];
                float scB = sscale[(np + 16) * 3 + sc];
                const float* bA = &sbase[np * 64];
                const float* bB = &sbase[(np + 16) * 64];
                #pragma unroll 8
                for (int j = 0; j < 64; j++) {
                    float a0 = bA[j] * scA;
                    float a1 = bB[j] * scB;
                    float4 w = spw4[j * 16 + oq];
                    acc0.x += a0 * w.x; acc0.y += a0 * w.y;
                    acc0.z += a0 * w.z; acc0.w += a0 * w.w;
                    acc1.x += a1 * w.x; acc1.y += a1 * w.y;
                    acc1.z += a1 * w.z; acc1.w += a1 * w.w;
                }
            }
        }
        int o = oq * 4;
        int idxA = sidx[np], idxB = sidx[np + 16];
        if (idxA >= 0) {
            float* h = &g_hidden[(size_t)idxA * 64 + o];
            h[0] += acc0.x + spb[o];     h[1] += acc0.y + spb[o + 1];
            h[2] += acc0.z + spb[o + 2]; h[3] += acc0.w + spb[o + 3];
        }
        if (idxB >= 0) {
            float* h = &g_hidden[(size_t)idxB * 64 + o];
            h[0] += acc1.x + spb[o];     h[1] += acc1.y + spb[o + 1];
            h[2] += acc1.z + spb[o + 2]; h[3] += acc1.w + spb[o + 3];
        }
    }
}

// ---------------- score MLP over active nodes, weights resident in smem ----------------
// dynamic smem layout (floats): slin[4096] sw1[8192] sw2[128] sb1[128] srp[256]
//                               sh[512] sx[512] sidx[8 ints]
#define SC2_FLOATS 13824
#define SC2_BYTES  ((SC2_FLOATS + 8) * 4)
__global__ void __launch_bounds__(256) k_score2(
        const float* __restrict__ linw, const float* __restrict__ w1,
        const float* __restrict__ b1, const float* __restrict__ w2,
        const float* __restrict__ b2) {
    extern __shared__ float smx[];
    float* slin = smx;             // [k][o] 64x64
    float* sw1  = smx + 4096;      // [j][c] 64x128
    float* sw2  = smx + 12288;     // 128
    float* sb1  = smx + 12416;     // 128
    float* srp  = smx + 12544;     // 4x64
    float* sh   = smx + 12800;     // 8x64
    float* sx   = smx + 13312;     // 8x64
    int*  sidx  = (int*)(smx + 13824);  // 8
    int t = threadIdx.x;
    #pragma unroll
    for (int q = 0; q < 16; q++) slin[q * 256 + t] = linw[q * 256 + t];
    #pragma unroll
    for (int q = 0; q < 32; q++) sw1[q * 256 + t] = w1[q * 256 + t];
    if (t < 128) { sw2[t] = w2[t]; sb1[t] = b1[t]; }
    srp[t] = g_relpart[t];         // 256 = BB*64
    float b2v = b2[0];
    int nact = g_nact;
    int ngroups = (nact + 7) >> 3;
    int w = t >> 5, lane = t & 31;
    const float4* sw14 = (const float4*)sw1;
    for (int g = blockIdx.x; g < ngroups; g += gridDim.x) {
        __syncthreads();
        if (t < 8) { int i = g * 8 + t; sidx[t] = (i < nact) ? g_act[i] : -1; }
        __syncthreads();
        #pragma unroll
        for (int q = 0; q < 2; q++) {
            int id = q * 256 + t;
            int nd = id >> 6, jj = id & 63;
            int idx = sidx[nd];
            sh[id] = (idx >= 0) ? g_hidden[(size_t)idx * 64 + jj] : 0.f;
        }
        __syncthreads();
        // phase 1: x = h * (h @ linW_top + relpart)   (warp w owns node w)
        {
            int idx = sidx[w];
            int bb = (idx >= 0) ? idx / NN : 0;
            int o = lane * 2;
            float a0 = srp[bb * 64 + o], a1 = srp[bb * 64 + o + 1];
            const float* hrow = &sh[w * 64];
            #pragma unroll 8
            for (int k = 0; k < 64; k++) {
                float hk = hrow[k];
                a0 += hk * slin[k * 64 + o];
                a1 += hk * slin[k * 64 + o + 1];
            }
            sx[w * 64 + o]     = hrow[o]     * a0;
            sx[w * 64 + o + 1] = hrow[o + 1] * a1;
        }
        __syncthreads();
        // phase 2: score = relu(x @ w1 + b1) . w2 + b2
        {
            int idx = sidx[w];
            int c = lane * 4;
            float4 a = {sb1[c], sb1[c + 1], sb1[c + 2], sb1[c + 3]};
            const float* xrow = &sx[w * 64];
            #pragma unroll 8
            for (int j = 0; j < 64; j++) {
                float xj = xrow[j];
                float4 wv = sw14[j * 32 + lane];
                a.x += xj * wv.x; a.y += xj * wv.y;
                a.z += xj * wv.z; a.w += xj * wv.w;
            }
            float p = fmaxf(a.x, 0.f) * sw2[c]     + fmaxf(a.y, 0.f) * sw2[c + 1]
                    + fmaxf(a.z, 0.f) * sw2[c + 2] + fmaxf(a.w, 0.f) * sw2[c + 3];
            #pragma unroll
            for (int off = 16; off > 0; off >>= 1)
                p += __shfl_xor_sync(0xFFFFFFFFu, p, off);
            if (lane == 0 && idx >= 0) g_score[idx] = p + b2v;
        }
    }
}

__global__ void k_out(const int* __restrict__ t_index, float* __restrict__ out) {
    int i = blockIdx.x * blockDim.x + threadIdx.x;
    if (i >= BB * TT) return;
    int b = i / TT;
    out[i] = g_score[(size_t)b * NN + t_index[i]];
}

// ---------------- launch sequence ----------------
extern "C" void kernel_launch(void* const* d_in, const int* in_sizes, int n_in,
                              void* d_out, int out_size) {
    const int*   h_index         = (const int*)d_in[0];
    const int*   r_index         = (const int*)d_in[1];
    const int*   t_index         = (const int*)d_in[2];
    const int*   all_index       = (const int*)d_in[3];
    const int*   edge_src        = (const int*)d_in[4];
    const int*   edge_dst        = (const int*)d_in[5];
    const int*   edge_type       = (const int*)d_in[6];
    const float* hidden_states   = (const float*)d_in[7];
    const float* score_text_embs = (const float*)d_in[8];
    const float* rel_table       = (const float*)d_in[9];
    const float* linear_w        = (const float*)d_in[10];
    const float* linear_b        = (const float*)d_in[11];
    const float* mlp_w1          = (const float*)d_in[12];
    const float* mlp_b1          = (const float*)d_in[13];
    const float* mlp_w2          = (const float*)d_in[14];
    const float* mlp_b2          = (const float*)d_in[15];
    const float* relw            = (const float*)d_in[16];
    const float* pna_w           = (const float*)d_in[17];
    const float* pna_b           = (const float*)d_in[18];
    float* out = (float*)d_out;
    (void)in_sizes; (void)n_in; (void)out_size;

    cudaFuncSetAttribute(k_score2, cudaFuncAttributeMaxDynamicSharedMemorySize, SC2_BYTES);

    // ---- setup ----
    k_init0<<<cdiv((long long)BB * NN * DD, 256), 256>>>();
    k_degfull<<<cdiv(EE, 256), 256>>>(edge_src);
    k_dmean<<<cdiv(NN, 256), 256>>>();
    k_dmean_fin<<<1, 1>>>();
    k_owner<<<cdiv(MM, 256), 256>>>(all_index);
    k_scatter<<<cdiv((long long)MM * DD, 256), 256>>>(all_index, score_text_embs);
    k_sethead<<<1, BB * DD>>>(h_index, hidden_states);
    k_relpart<<<BB, DD>>>(r_index, rel_table, linear_w, linear_b);
    k_base<<<1, 128>>>(mlp_b1, mlp_w2, mlp_b2);
    k_scorefill<<<cdiv(BB * NN, 256), 256>>>();
    k_score_head<<<dim3(1, BB), 128>>>(h_index, linear_w, mlp_w1, mlp_b1, mlp_w2, mlp_b2);

    for (int l = 0; l < LL; l++) {
        const float* relw_l = relw + (size_t)l * R2C * DD;
        const float* pw     = pna_w + (size_t)l * 12 * DD * DD;
        const float* pb     = pna_b + (size_t)l * DD;

        // ---- node top-K (exact, tie-break lower index) ----
        k_selinit_nodes<<<1, 32>>>();
        k_nkeys<<<dim3(cdiv(NN, 256), BB), 256>>>();
        for (int p = 0; p < 4; p++) {
            int shift = 48 - 16 * p;
            int srcA = ((p & 1) == 0) ? 1 : 0;
            k_zerohist<<<cdiv(BB * NBINS, 256), 256>>>();
            k_hist<<<dim3(cdiv(NN, 256), BB), 256>>>(srcA, shift);
            k_pick<<<BB, 1024>>>(shift, srcA);
            if (p < 3) k_compact<<<dim3(cdiv(NN, 256), BB), 256>>>(srcA, shift);
        }
        k_marksel<<<dim3(cdiv(NN, 256), BB), 256>>>();

        // ---- edge top-ESEL among finite (sel-src) edges ----
        k_selinit_edges<<<1, 32>>>();
        k_ekeys<<<dim3(cdiv(EE, 256), BB), 256>>>(edge_src, edge_dst);
        k_clampkth<<<1, 32>>>();
        for (int p = 0; p < 4; p++) {
            int shift = 48 - 16 * p;
            int srcA = ((p & 1) == 0) ? 1 : 0;
            k_zerohist<<<cdiv(BB * NBINS, 256), 256>>>();
            k_hist<<<dim3(cdiv(EE, 256), BB), 256>>>(srcA, shift);
            k_pick<<<BB, 1024>>>(shift, srcA);
            if (p < 3) k_compact<<<dim3(cdiv(EE, 256), BB), 256>>>(srcA, shift);
        }
        k_markedges<<<dim3(cdiv(EE, 256), BB), 256>>>(edge_src, edge_dst);

        // ---- aggregate + PNA update + rescore ----
        k_aggfill4<<<cdiv((long long)BB * NN * DD / 4, 256), 256>>>();
        k_msg<<<dim3(cdiv(ESELC, 4), BB), 256>>>(edge_src, edge_dst, edge_type, relw_l);
        k_prep<<<dim3(NN, BB), DD>>>();
        k_pnagemm<<<1184, 256>>>(pw, pb);
        k_score2<<<592, 256, SC2_BYTES>>>(linear_w, mlp_w1, mlp_b1, mlp_w2, mlp_b2);
    }

    k_out<<<cdiv(BB * TT, 128), 128>>>(t_index, out);
}

// round 16
// speedup vs baseline: 1.5428x; 1.2171x over previous
#include <cuda_runtime.h>
#include <math.h>

// ---------------- problem constants ----------------
#define BB   4
#define NN   50000
#define EE   1600000
#define DD   64
#define R2C  1000
#define TT   32
#define MM   10000
#define LL   3
#define KK   5000        // nodes kept per layer
#define ESELC 160000     // edges kept per layer
#define NBINS 65536      // 16-bit radix digits
#define SCAN_N (BB * NN)
#define SCAN_BLOCKS 782  // cdiv(200000, 256)

typedef unsigned long long u64;
typedef unsigned int u32;

static inline int cdiv(long long a, long long b) { return (int)((a + b - 1) / b); }

// ---------------- device scratch (no allocation allowed) ----------------
__device__ float g_hidden[(size_t)BB * NN * DD];
__device__ float g_sumA [(size_t)BB * NN * DD];   // mean (active nodes only)
__device__ float g_sqA  [(size_t)BB * NN * DD];   // std
__device__ float g_mxA  [(size_t)BB * NN * DD];   // max
__device__ float g_mnA  [(size_t)BB * NN * DD];   // min
__device__ float g_score[BB * NN];
__device__ unsigned char g_sel[BB * NN];
__device__ float g_relpart[BB * DD];
__device__ float g_degfull[NN];
__device__ int   g_owner[NN];
__device__ float g_dmean_sum;
__device__ float g_dmean;
__device__ float g_base;
__device__ u64   g_keyA[(size_t)BB * EE];
__device__ u64   g_keyB[(size_t)BB * EE];
__device__ int   g_cntA[BB];
__device__ int   g_cntB[BB];
__device__ u64   g_thresh[BB];
__device__ int   g_kth[BB];
__device__ u32   g_hist[BB * NBINS];
__device__ int   g_seledge[BB * ESELC];
__device__ int   g_nsel[BB];
// CSR + active-node machinery
__device__ int   g_cnt[SCAN_N];
__device__ int   g_off[SCAN_N];
__device__ int   g_bsum[1024];
__device__ int   g_csr[BB * ESELC];
__device__ int   g_act[SCAN_N];
__device__ float g_amp[SCAN_N];
__device__ float g_att[SCAN_N];
__device__ int   g_nact;

// ---------------- helpers ----------------
__device__ __forceinline__ u32 ford(float f) {
    u32 u = __float_as_uint(f);
    return (u & 0x80000000u) ? ~u : (u | 0x80000000u);  // order-preserving float->uint
}

// ---------------- setup kernels ----------------
__global__ void k_init0() {
    size_t i = (size_t)blockIdx.x * blockDim.x + threadIdx.x;
    if (i < (size_t)BB * NN * DD) g_hidden[i] = 0.f;
    if (i < NN) { g_degfull[i] = 0.f; g_owner[i] = -1; }
    if (i == 0) g_dmean_sum = 0.f;
}

__global__ void k_degfull(const int* __restrict__ esrc) {
    int e = blockIdx.x * blockDim.x + threadIdx.x;
    if (e < EE) atomicAdd(&g_degfull[esrc[e]], 1.f);
}

__global__ void k_dmean() {
    __shared__ float s[256];
    int i = blockIdx.x * 256 + threadIdx.x;
    float v = 0.f;
    if (i < NN) v = logf(g_degfull[i] + 1.f);
    s[threadIdx.x] = v;
    __syncthreads();
    for (int o = 128; o > 0; o >>= 1) {
        if (threadIdx.x < o) s[threadIdx.x] += s[threadIdx.x + o];
        __syncthreads();
    }
    if (threadIdx.x == 0) atomicAdd(&g_dmean_sum, s[0]);
}
__global__ void k_dmean_fin() { g_dmean = g_dmean_sum / (float)NN; }

// last-occurrence-wins ownership for duplicate scatter indices
__global__ void k_owner(const int* __restrict__ all_index) {
    int m = blockIdx.x * blockDim.x + threadIdx.x;
    if (m < MM) atomicMax(&g_owner[all_index[m]], m);
}
__global__ void k_scatter(const int* __restrict__ all_index, const float* __restrict__ embs) {
    int id = blockIdx.x * blockDim.x + threadIdx.x;
    if (id >= MM * DD) return;
    int m = id / DD, j = id % DD;
    int idx = all_index[m];
    if (g_owner[idx] != m) return;
    float v = embs[(size_t)m * DD + j];
    for (int b = 0; b < BB; b++)
        g_hidden[((size_t)b * NN + idx) * DD + j] = v;
}
__global__ void k_sethead(const int* __restrict__ h_index, const float* __restrict__ hs) {
    int id = threadIdx.x;  // BB*DD = 256 threads
    int b = id / DD, j = id % DD;
    int h = h_index[b];
    g_hidden[((size_t)b * NN + h) * DD + j] = hs[b * DD + j];
}

// rel_part[b] = rel @ W_bottom + linear_b
__global__ void k_relpart(const int* __restrict__ r_index, const float* __restrict__ rel_table,
                          const float* __restrict__ linear_w, const float* __restrict__ linear_b) {
    int b = blockIdx.x, j = threadIdx.x;  // 64 threads
    const float* rel = rel_table + (size_t)r_index[b] * DD;
    float acc = linear_b[j];
    for (int k = 0; k < DD; k++) acc += rel[k] * linear_w[(DD + k) * DD + j];
    g_relpart[b * DD + j] = acc;
}

// base = score_fn(0) = relu(b1) @ w2 + b2 (rel-independent)
__global__ void k_base(const float* __restrict__ mlp_b1, const float* __restrict__ mlp_w2,
                       const float* __restrict__ mlp_b2) {
    __shared__ float s[128];
    int t = threadIdx.x;
    s[t] = fmaxf(mlp_b1[t], 0.f) * mlp_w2[t];
    __syncthreads();
    for (int o = 64; o > 0; o >>= 1) {
        if (t < o) s[t] += s[t + o];
        __syncthreads();
    }
    if (t == 0) g_base = s[0] + mlp_b2[0];
}
__global__ void k_scorefill() {
    int i = blockIdx.x * blockDim.x + threadIdx.x;
    if (i < BB * NN) g_score[i] = g_base;
}

// initial head-only scoring (runs once; not perf-critical)
__global__ void __launch_bounds__(128) k_score_head(
        const int* __restrict__ h_index,
        const float* __restrict__ linear_w,
        const float* __restrict__ mlp_w1, const float* __restrict__ mlp_b1,
        const float* __restrict__ mlp_w2, const float* __restrict__ mlp_b2) {
    int b = blockIdx.y;
    int n = h_index[b];
    int t = threadIdx.x;  // 128
    __shared__ float sh[DD], sx[DD], sr[128];
    if (t < DD) sh[t] = g_hidden[((size_t)b * NN + n) * DD + t];
    __syncthreads();
    if (t < DD) {
        float acc = g_relpart[b * DD + t];
        #pragma unroll 8
        for (int k = 0; k < DD; k++) acc += sh[k] * linear_w[k * DD + t];
        sx[t] = sh[t] * acc;
    }
    __syncthreads();
    float h1 = mlp_b1[t];
    #pragma unroll 8
    for (int j = 0; j < DD; j++) h1 += sx[j] * mlp_w1[j * 128 + t];
    h1 = fmaxf(h1, 0.f);
    sr[t] = h1 * mlp_w2[t];
    __syncthreads();
    for (int o = 64; o > 0; o >>= 1) {
        if (t < o) sr[t] += sr[t + o];
        __syncthreads();
    }
    if (t == 0) g_score[b * NN + n] = sr[0] + mlp_b2[0];
}

// ---------------- radix-select machinery (16-bit digits, 4 passes) ----------------
__global__ void k_selinit_nodes() {
    int b = threadIdx.x;
    if (b < BB) { g_cntA[b] = NN; g_kth[b] = KK; g_thresh[b] = 0ull; }
}
__global__ void k_selinit_edges() {
    int b = threadIdx.x;
    if (b < BB) { g_cntA[b] = 0; g_thresh[b] = 0ull; g_nsel[b] = 0; }
}
__global__ void k_clampkth() {
    int b = threadIdx.x;
    if (b < BB) g_kth[b] = min(ESELC, g_cntA[b]);
}
__global__ void k_nkeys() {
    int b = blockIdx.y;
    int n = blockIdx.x * blockDim.x + threadIdx.x;
    if (n >= NN) return;
    u64 key = ((u64)ford(g_score[b * NN + n]) << 32) | (u32)(0x7FFFFFFF - n);
    g_keyA[(size_t)b * EE + n] = key;
}
__global__ void k_ekeys(const int* __restrict__ esrc, const int* __restrict__ edst) {
    int b = blockIdx.y;
    int e = blockIdx.x * blockDim.x + threadIdx.x;
    if (e >= EE) return;
    if (!g_sel[b * NN + esrc[e]]) return;
    u64 key = ((u64)ford(g_score[b * NN + edst[e]]) << 32) | (u32)(0x7FFFFFFF - e);
    int p = atomicAdd(&g_cntA[b], 1);
    g_keyA[(size_t)b * EE + p] = key;
}
__global__ void k_zerohist() {
    int i = blockIdx.x * blockDim.x + threadIdx.x;
    if (i < BB * NBINS) g_hist[i] = 0u;
}
__global__ void k_hist(int srcIsA, int shift) {
    int b = blockIdx.y;
    int idx = blockIdx.x * blockDim.x + threadIdx.x;
    int cnt = srcIsA ? g_cntA[b] : g_cntB[b];
    if (idx >= cnt) return;
    const u64* s = srcIsA ? g_keyA : g_keyB;
    u32 bucket = (u32)((s[(size_t)b * EE + idx] >> shift) & 0xFFFFull);
    atomicAdd(&g_hist[b * NBINS + bucket], 1u);
}
__global__ void __launch_bounds__(1024) k_pick(int shift, int srcIsA) {
    int b = blockIdx.x;
    int t = threadIdx.x;  // 1024
    const u32* h = &g_hist[b * NBINS];
    int hi = 65535 - t * 64;
    int partial = 0;
    #pragma unroll
    for (int i = 0; i < 64; i++) partial += (int)h[hi - i];
    __shared__ int sp[1024];
    sp[t] = partial;
    __syncthreads();
    for (int off = 1; off < 1024; off <<= 1) {
        int v = (t >= off) ? sp[t - off] : 0;
        __syncthreads();
        sp[t] += v;
        __syncthreads();
    }
    int incl = sp[t];
    int excl = incl - partial;
    int k = g_kth[b];
    if (k >= 1 && excl < k && incl >= k) {
        int cum = excl;
        for (int i = 0; i < 64; i++) {
            int c = (int)h[hi - i];
            cum += c;
            if (cum >= k) {
                g_thresh[b] |= ((u64)(u32)(hi - i)) << shift;
                g_kth[b] = k - (cum - c);
                break;
            }
        }
    }
    if (t == 0) {
        if (srcIsA) g_cntB[b] = 0; else g_cntA[b] = 0;
    }
}
__global__ void k_compact(int srcIsA, int shift) {
    int b = blockIdx.y;
    int idx = blockIdx.x * blockDim.x + threadIdx.x;
    int cnt = srcIsA ? g_cntA[b] : g_cntB[b];
    if (idx >= cnt) return;
    const u64* s = srcIsA ? g_keyA : g_keyB;
    u64* d = srcIsA ? g_keyB : g_keyA;
    u64 key = s[(size_t)b * EE + idx];
    if (((key >> shift) & 0xFFFFull) == ((g_thresh[b] >> shift) & 0xFFFFull)) {
        int p = atomicAdd(srcIsA ? &g_cntB[b] : &g_cntA[b], 1);
        d[(size_t)b * EE + p] = key;
    }
}
__global__ void k_marksel() {
    int b = blockIdx.y;
    int n = blockIdx.x * blockDim.x + threadIdx.x;
    if (n >= NN) return;
    u64 key = ((u64)ford(g_score[b * NN + n]) << 32) | (u32)(0x7FFFFFFF - n);
    g_sel[b * NN + n] = (key >= g_thresh[b]) ? 1 : 0;
}
__global__ void k_markedges(const int* __restrict__ esrc, const int* __restrict__ edst) {
    int b = blockIdx.y;
    int e = blockIdx.x * blockDim.x + threadIdx.x;
    if (e >= EE) return;
    if (!g_sel[b * NN + esrc[e]]) return;
    u64 key = ((u64)ford(g_score[b * NN + edst[e]]) << 32) | (u32)(0x7FFFFFFF - e);
    if (key >= g_thresh[b]) {
        int p = atomicAdd(&g_nsel[b], 1);
        if (p < ESELC) g_seledge[b * ESELC + p] = e;
    }
}

// ---------------- CSR build + gather aggregation ----------------
__global__ void k_clearcnt() {
    int i = blockIdx.x * blockDim.x + threadIdx.x;
    if (i < SCAN_N) g_cnt[i] = 0;
    if (i == 0) g_nact = 0;
}
__global__ void k_count(const int* __restrict__ edst) {
    int b = blockIdx.y;
    int i = blockIdx.x * blockDim.x + threadIdx.x;
    if (i >= g_nsel[b]) return;
    int e = g_seledge[b * ESELC + i];
    int idx = b * NN + edst[e];
    int old = atomicAdd(&g_cnt[idx], 1);
    if (old == 0) {
        int p = atomicAdd(&g_nact, 1);
        g_act[p] = idx;
    }
}
__global__ void __launch_bounds__(256) k_scan1() {
    __shared__ int s[256];
    int b = blockIdx.x, t = threadIdx.x;
    int i = b * 256 + t;
    int v = (i < SCAN_N) ? g_cnt[i] : 0;
    s[t] = v;
    __syncthreads();
    for (int off = 1; off < 256; off <<= 1) {
        int u = (t >= off) ? s[t - off] : 0;
        __syncthreads();
        s[t] += u;
        __syncthreads();
    }
    if (i < SCAN_N) g_off[i] = s[t];  // inclusive within block
    if (t == 255) g_bsum[b] = s[255];
}
__global__ void __launch_bounds__(1024) k_scan2() {
    __shared__ int s[1024];
    int t = threadIdx.x;
    int v = (t < SCAN_BLOCKS) ? g_bsum[t] : 0;
    s[t] = v;
    __syncthreads();
    for (int off = 1; off < 1024; off <<= 1) {
        int u = (t >= off) ? s[t - off] : 0;
        __syncthreads();
        s[t] += u;
        __syncthreads();
    }
    if (t < SCAN_BLOCKS) g_bsum[t] = s[t] - v;  // exclusive
}
__global__ void k_scan3() {
    int b = blockIdx.x, t = threadIdx.x;
    int i = b * 256 + t;
    if (i < SCAN_N) g_off[i] = g_off[i] - g_cnt[i] + g_bsum[b];  // exclusive start
}
__global__ void k_fill(const int* __restrict__ edst) {
    int b = blockIdx.y;
    int i = blockIdx.x * blockDim.x + threadIdx.x;
    if (i >= g_nsel[b]) return;
    int e = g_seledge[b * ESELC + i];
    int idx = b * NN + edst[e];
    int pos = atomicAdd(&g_off[idx], 1);   // g_off becomes end-offset
    g_csr[pos] = e;
}

// gather: one node per 64 threads, 4 nodes per block; registers-only aggregation
__global__ void __launch_bounds__(256) k_gather(
        const int* __restrict__ esrc, const int* __restrict__ etyp,
        const float* __restrict__ relw_l) {
    int t = threadIdx.x;
    int j = t & 63, slot = t >> 6;
    int nact = g_nact;
    int ngr = (nact + 3) >> 2;
    for (int g = blockIdx.x; g < ngr; g += gridDim.x) {
        int i = g * 4 + slot;
        if (i >= nact) continue;
        int idx = g_act[i];
        int b = idx / NN;
        int end = g_off[idx], cnt = g_cnt[idx], start = end - cnt;
        float sum = 0.f, sq = 0.f, mx = -INFINITY, mn = INFINITY;
        for (int k = start; k < end; k++) {
            int e = g_csr[k];
            int s = esrc[e], et = etyp[e];
            float gate = 1.f / (1.f + expf(-g_score[b * NN + s]));
            float m = gate * g_hidden[((size_t)b * NN + s) * DD + j]
                           * relw_l[(size_t)et * DD + j];
            sum += m; sq += m * m;
            mx = fmaxf(mx, m); mn = fminf(mn, m);
        }
        float degc = (float)cnt;  // cnt >= 1 for active nodes
        float mean = sum / degc;
        float stdv = sqrtf(fmaxf(sq / degc - mean * mean, 0.f) + 1e-6f);
        size_t o = (size_t)idx * DD + j;
        g_sumA[o] = mean; g_sqA[o] = stdv; g_mxA[o] = mx; g_mnA[o] = mn;
        if (j == 0) {
            float logd = logf(degc + 1.f);
            float dm = g_dmean;
            g_amp[idx] = logd / dm;
            g_att[idx] = dm / fmaxf(logd, 1e-6f);
        }
    }
}

// ---------------- PNA GEMM: 64-node tiles, 16 accumulators/thread ----------------
__global__ void __launch_bounds__(256) k_pnagemm(const float* __restrict__ pw,
                                                 const float* __restrict__ pb) {
    __shared__ float spw[4096];      // current pw chunk [j][o]
    __shared__ float sbase[4096];    // current agg base [nd][j] (broadcast reads)
    __shared__ float sscale[64 * 3];
    __shared__ int   sidx[64];
    __shared__ float spb[64];
    int t = threadIdx.x;
    if (t < 64) spb[t] = pb[t];
    int nact = g_nact;
    int ngroups = (nact + 63) >> 6;
    int oq = t & 15;     // 4 output cols: oq*4..oq*4+3
    int np = t >> 4;     // nodes np, np+16, np+32, np+48
    float4* spw4 = (float4*)spw;
    for (int g = blockIdx.x; g < ngroups; g += gridDim.x) {
        __syncthreads();  // previous group done with sidx/sscale/spw/sbase
        if (t < 64) {
            int i = g * 64 + t;
            int idx = (i < nact) ? g_act[i] : -1;
            sidx[t] = idx;
            if (idx >= 0) {
                sscale[t * 3 + 0] = 1.f;
                sscale[t * 3 + 1] = g_amp[idx];
                sscale[t * 3 + 2] = g_att[idx];
            } else {
                sscale[t * 3 + 0] = 0.f; sscale[t * 3 + 1] = 0.f; sscale[t * 3 + 2] = 0.f;
            }
        }
        __syncthreads();
        float4 acc[4];
        #pragma unroll
        for (int q = 0; q < 4; q++) acc[q] = make_float4(0.f, 0.f, 0.f, 0.f);
        for (int agg = 0; agg < 4; agg++) {
            const float* src = (agg == 0) ? g_sumA : (agg == 1) ? g_mxA
                              : (agg == 2) ? g_mnA : g_sqA;
            __syncthreads();  // previous compute done reading sbase
            #pragma unroll
            for (int q = 0; q < 16; q++) {
                int id = q * 256 + t;       // 4096 = 64 nodes x 64 dims
                int nd = id >> 6, jj = id & 63;
                int idx = sidx[nd];
                sbase[id] = (idx >= 0) ? src[(size_t)idx * 64 + jj] : 0.f;
            }
            for (int sc = 0; sc < 3; sc++) {
                __syncthreads();  // prev compute done reading spw; sbase fill visible
                const float4* pws = (const float4*)(pw + (size_t)(agg * 3 + sc) * 4096);
                #pragma unroll
                for (int q = 0; q < 4; q++) spw4[q * 256 + t] = pws[q * 256 + t];
                __syncthreads();
                float s0 = sscale[np * 3 + sc];
                float s1 = sscale[(np + 16) * 3 + sc];
                float s2 = sscale[(np + 32) * 3 + sc];
                float s3 = sscale[(np + 48) * 3 + sc];
                #pragma unroll 4
                for (int j = 0; j < 64; j++) {
                    float4 w = spw4[j * 16 + oq];
                    float a0 = sbase[np * 64 + j] * s0;
                    float a1 = sbase[(np + 16) * 64 + j] * s1;
                    float a2 = sbase[(np + 32) * 64 + j] * s2;
                    float a3 = sbase[(np + 48) * 64 + j] * s3;
                    acc[0].x += a0 * w.x; acc[0].y += a0 * w.y; acc[0].z += a0 * w.z; acc[0].w += a0 * w.w;
                    acc[1].x += a1 * w.x; acc[1].y += a1 * w.y; acc[1].z += a1 * w.z; acc[1].w += a1 * w.w;
                    acc[2].x += a2 * w.x; acc[2].y += a2 * w.y; acc[2].z += a2 * w.z; acc[2].w += a2 * w.w;
                    acc[3].x += a3 * w.x; acc[3].y += a3 * w.y; acc[3].z += a3 * w.z; acc[3].w += a3 * w.w;
                }
            }
        }
        int o = oq * 4;
        #pragma unroll
        for (int q = 0; q < 4; q++) {
            int idx = sidx[np + 16 * q];
            if (idx >= 0) {
                float* h = &g_hidden[(size_t)idx * 64 + o];
                h[0] += acc[q].x + spb[o];     h[1] += acc[q].y + spb[o + 1];
                h[2] += acc[q].z + spb[o + 2]; h[3] += acc[q].w + spb[o + 3];
            }
        }
    }
}

// ---------------- score MLP over active nodes, weights resident in smem ----------------
#define SC2_FLOATS 13824
#define SC2_BYTES  ((SC2_FLOATS + 8) * 4)
__global__ void __launch_bounds__(256) k_score2(
        const float* __restrict__ linw, const float* __restrict__ w1,
        const float* __restrict__ b1, const float* __restrict__ w2,
        const float* __restrict__ b2) {
    extern __shared__ float smx[];
    float* slin = smx;             // [k][o] 64x64
    float* sw1  = smx + 4096;      // [j][c] 64x128
    float* sw2  = smx + 12288;     // 128
    float* sb1  = smx + 12416;     // 128
    float* srp  = smx + 12544;     // 4x64
    float* sh   = smx + 12800;     // 8x64
    float* sx   = smx + 13312;     // 8x64
    int*  sidx  = (int*)(smx + 13824);  // 8
    int t = threadIdx.x;
    #pragma unroll
    for (int q = 0; q < 16; q++) slin[q * 256 + t] = linw[q * 256 + t];
    #pragma unroll
    for (int q = 0; q < 32; q++) sw1[q * 256 + t] = w1[q * 256 + t];
    if (t < 128) { sw2[t] = w2[t]; sb1[t] = b1[t]; }
    srp[t] = g_relpart[t];         // 256 = BB*64
    float b2v = b2[0];
    int nact = g_nact;
    int ngroups = (nact + 7) >> 3;
    int w = t >> 5, lane = t & 31;
    const float4* sw14 = (const float4*)sw1;
    for (int g = blockIdx.x; g < ngroups; g += gridDim.x) {
        __syncthreads();
        if (t < 8) { int i = g * 8 + t; sidx[t] = (i < nact) ? g_act[i] : -1; }
        __syncthreads();
        #pragma unroll
        for (int q = 0; q < 2; q++) {
            int id = q * 256 + t;
            int nd = id >> 6, jj = id & 63;
            int idx = sidx[nd];
            sh[id] = (idx >= 0) ? g_hidden[(size_t)idx * 64 + jj] : 0.f;
        }
        __syncthreads();
        // phase 1: x = h * (h @ linW_top + relpart)   (warp w owns node w)
        {
            int idx = sidx[w];
            int bb = (idx >= 0) ? idx / NN : 0;
            int o = lane * 2;
            float a0 = srp[bb * 64 + o], a1 = srp[bb * 64 + o + 1];
            const float* hrow = &sh[w * 64];
            #pragma unroll 8
            for (int k = 0; k < 64; k++) {
                float hk = hrow[k];
                a0 += hk * slin[k * 64 + o];
                a1 += hk * slin[k * 64 + o + 1];
            }
            sx[w * 64 + o]     = hrow[o]     * a0;
            sx[w * 64 + o + 1] = hrow[o + 1] * a1;
        }
        __syncthreads();
        // phase 2: score = relu(x @ w1 + b1) . w2 + b2
        {
            int idx = sidx[w];
            int c = lane * 4;
            float4 a = {sb1[c], sb1[c + 1], sb1[c + 2], sb1[c + 3]};
            const float* xrow = &sx[w * 64];
            #pragma unroll 8
            for (int j = 0; j < 64; j++) {
                float xj = xrow[j];
                float4 wv = sw14[j * 32 + lane];
                a.x += xj * wv.x; a.y += xj * wv.y;
                a.z += xj * wv.z; a.w += xj * wv.w;
            }
            float p = fmaxf(a.x, 0.f) * sw2[c]     + fmaxf(a.y, 0.f) * sw2[c + 1]
                    + fmaxf(a.z, 0.f) * sw2[c + 2] + fmaxf(a.w, 0.f) * sw2[c + 3];
            #pragma unroll
            for (int off = 16; off > 0; off >>= 1)
                p += __shfl_xor_sync(0xFFFFFFFFu, p, off);
            if (lane == 0 && idx >= 0) g_score[idx] = p + b2v;
        }
    }
}

__global__ void k_out(const int* __restrict__ t_index, float* __restrict__ out) {
    int i = blockIdx.x * blockDim.x + threadIdx.x;
    if (i >= BB * TT) return;
    int b = i / TT;
    out[i] = g_score[(size_t)b * NN + t_index[i]];
}

// ---------------- launch sequence ----------------
extern "C" void kernel_launch(void* const* d_in, const int* in_sizes, int n_in,
                              void* d_out, int out_size) {
    const int*   h_index         = (const int*)d_in[0];
    const int*   r_index         = (const int*)d_in[1];
    const int*   t_index         = (const int*)d_in[2];
    const int*   all_index       = (const int*)d_in[3];
    const int*   edge_src        = (const int*)d_in[4];
    const int*   edge_dst        = (const int*)d_in[5];
    const int*   edge_type       = (const int*)d_in[6];
    const float* hidden_states   = (const float*)d_in[7];
    const float* score_text_embs = (const float*)d_in[8];
    const float* rel_table       = (const float*)d_in[9];
    const float* linear_w        = (const float*)d_in[10];
    const float* linear_b        = (const float*)d_in[11];
    const float* mlp_w1          = (const float*)d_in[12];
    const float* mlp_b1          = (const float*)d_in[13];
    const float* mlp_w2          = (const float*)d_in[14];
    const float* mlp_b2          = (const float*)d_in[15];
    const float* relw            = (const float*)d_in[16];
    const float* pna_w           = (const float*)d_in[17];
    const float* pna_b           = (const float*)d_in[18];
    float* out = (float*)d_out;
    (void)in_sizes; (void)n_in; (void)out_size;

    cudaFuncSetAttribute(k_score2, cudaFuncAttributeMaxDynamicSharedMemorySize, SC2_BYTES);

    // ---- setup ----
    k_init0<<<cdiv((long long)BB * NN * DD, 256), 256>>>();
    k_degfull<<<cdiv(EE, 256), 256>>>(edge_src);
    k_dmean<<<cdiv(NN, 256), 256>>>();
    k_dmean_fin<<<1, 1>>>();
    k_owner<<<cdiv(MM, 256), 256>>>(all_index);
    k_scatter<<<cdiv((long long)MM * DD, 256), 256>>>(all_index, score_text_embs);
    k_sethead<<<1, BB * DD>>>(h_index, hidden_states);
    k_relpart<<<BB, DD>>>(r_index, rel_table, linear_w, linear_b);
    k_base<<<1, 128>>>(mlp_b1, mlp_w2, mlp_b2);
    k_scorefill<<<cdiv(BB * NN, 256), 256>>>();
    k_score_head<<<dim3(1, BB), 128>>>(h_index, linear_w, mlp_w1, mlp_b1, mlp_w2, mlp_b2);

    for (int l = 0; l < LL; l++) {
        const float* relw_l = relw + (size_t)l * R2C * DD;
        const float* pw     = pna_w + (size_t)l * 12 * DD * DD;
        const float* pb     = pna_b + (size_t)l * DD;

        // ---- node top-K (exact, tie-break lower index) ----
        k_selinit_nodes<<<1, 32>>>();
        k_nkeys<<<dim3(cdiv(NN, 256), BB), 256>>>();
        for (int p = 0; p < 4; p++) {
            int shift = 48 - 16 * p;
            int srcA = ((p & 1) == 0) ? 1 : 0;
            k_zerohist<<<cdiv(BB * NBINS, 256), 256>>>();
            k_hist<<<dim3(cdiv(NN, 256), BB), 256>>>(srcA, shift);
            k_pick<<<BB, 1024>>>(shift, srcA);
            if (p < 3) k_compact<<<dim3(cdiv(NN, 256), BB), 256>>>(srcA, shift);
        }
        k_marksel<<<dim3(cdiv(NN, 256), BB), 256>>>();

        // ---- edge top-ESEL among finite (sel-src) edges ----
        k_selinit_edges<<<1, 32>>>();
        k_ekeys<<<dim3(cdiv(EE, 256), BB), 256>>>(edge_src, edge_dst);
        k_clampkth<<<1, 32>>>();
        for (int p = 0; p < 4; p++) {
            int shift = 48 - 16 * p;
            int srcA = ((p & 1) == 0) ? 1 : 0;
            k_zerohist<<<cdiv(BB * NBINS, 256), 256>>>();
            k_hist<<<dim3(cdiv(EE, 256), BB), 256>>>(srcA, shift);
            k_pick<<<BB, 1024>>>(shift, srcA);
            if (p < 3) k_compact<<<dim3(cdiv(EE, 256), BB), 256>>>(srcA, shift);
        }
        k_markedges<<<dim3(cdiv(EE, 256), BB), 256>>>(edge_src, edge_dst);

        // ---- CSR build + gather aggregation ----
        k_clearcnt<<<SCAN_BLOCKS, 256>>>();
        k_count<<<dim3(cdiv(ESELC, 256), BB), 256>>>(edge_dst);
        k_scan1<<<SCAN_BLOCKS, 256>>>();
        k_scan2<<<1, 1024>>>();
        k_scan3<<<SCAN_BLOCKS, 256>>>();
        k_fill<<<dim3(cdiv(ESELC, 256), BB), 256>>>(edge_dst);
        k_gather<<<2048, 256>>>(edge_src, edge_type, relw_l);

        // ---- PNA update + rescore ----
        k_pnagemm<<<1184, 256>>>(pw, pb);
        k_score2<<<592, 256, SC2_BYTES>>>(linear_w, mlp_w1, mlp_b1, mlp_w2, mlp_b2);
    }

    k_out<<<cdiv(BB * TT, 128), 128>>>(t_index, out);
}

// round 17
// speedup vs baseline: 1.9062x; 1.2355x over previous
#include <cuda_runtime.h>
#include <math.h>

// ---------------- problem constants ----------------
#define BB   4
#define NN   50000
#define EE   1600000
#define DD   64
#define R2C  1000
#define TT   32
#define MM   10000
#define LL   3
#define KK   5000        // nodes kept per layer
#define ESELC 160000     // edges kept per layer
#define SCAN_N (BB * NN)
#define SCAN_BLOCKS 782  // cdiv(200000, 256)

typedef unsigned long long u64;
typedef unsigned int u32;

static inline int cdiv(long long a, long long b) { return (int)((a + b - 1) / b); }

// ---------------- device scratch (no allocation allowed) ----------------
__device__ float g_hidden[(size_t)BB * NN * DD];
__device__ float g_sumA [(size_t)BB * NN * DD];   // mean (active nodes only)
__device__ float g_sqA  [(size_t)BB * NN * DD];   // std
__device__ float g_mxA  [(size_t)BB * NN * DD];   // max
__device__ float g_mnA  [(size_t)BB * NN * DD];   // min
__device__ float g_score[BB * NN];
__device__ unsigned char g_sel[BB * NN];
__device__ float g_relpart[BB * DD];
__device__ float g_degfull[NN];
__device__ int   g_owner[NN];
__device__ float g_dmean_sum;
__device__ float g_dmean;
__device__ float g_base;
__device__ u64   g_keyA[(size_t)BB * EE];
__device__ u64   g_keyB[(size_t)BB * EE];
__device__ int   g_cntA[BB];
__device__ u64   g_thresh[BB];
__device__ int   g_seledge[BB * ESELC];
__device__ int   g_nsel[BB];
// CSR + active-node machinery
__device__ int   g_cnt[SCAN_N];
__device__ int   g_off[SCAN_N];
__device__ int   g_bsum[1024];
__device__ int   g_csr[BB * ESELC];
__device__ int   g_act[SCAN_N];
__device__ float g_amp[SCAN_N];
__device__ float g_att[SCAN_N];
__device__ int   g_nact;

// ---------------- helpers ----------------
__device__ __forceinline__ u32 ford(float f) {
    u32 u = __float_as_uint(f);
    return (u & 0x80000000u) ? ~u : (u | 0x80000000u);  // order-preserving float->uint
}

// ---------------- setup kernels ----------------
__global__ void k_init0() {
    size_t i = (size_t)blockIdx.x * blockDim.x + threadIdx.x;
    if (i < (size_t)BB * NN * DD) g_hidden[i] = 0.f;
    if (i < NN) { g_degfull[i] = 0.f; g_owner[i] = -1; }
    if (i == 0) g_dmean_sum = 0.f;
}

__global__ void k_degfull(const int* __restrict__ esrc) {
    int e = blockIdx.x * blockDim.x + threadIdx.x;
    if (e < EE) atomicAdd(&g_degfull[esrc[e]], 1.f);
}

__global__ void k_dmean() {
    __shared__ float s[256];
    int i = blockIdx.x * 256 + threadIdx.x;
    float v = 0.f;
    if (i < NN) v = logf(g_degfull[i] + 1.f);
    s[threadIdx.x] = v;
    __syncthreads();
    for (int o = 128; o > 0; o >>= 1) {
        if (threadIdx.x < o) s[threadIdx.x] += s[threadIdx.x + o];
        __syncthreads();
    }
    if (threadIdx.x == 0) atomicAdd(&g_dmean_sum, s[0]);
}
__global__ void k_dmean_fin() { g_dmean = g_dmean_sum / (float)NN; }

// last-occurrence-wins ownership for duplicate scatter indices
__global__ void k_owner(const int* __restrict__ all_index) {
    int m = blockIdx.x * blockDim.x + threadIdx.x;
    if (m < MM) atomicMax(&g_owner[all_index[m]], m);
}
__global__ void k_scatter(const int* __restrict__ all_index, const float* __restrict__ embs) {
    int id = blockIdx.x * blockDim.x + threadIdx.x;
    if (id >= MM * DD) return;
    int m = id / DD, j = id % DD;
    int idx = all_index[m];
    if (g_owner[idx] != m) return;
    float v = embs[(size_t)m * DD + j];
    for (int b = 0; b < BB; b++)
        g_hidden[((size_t)b * NN + idx) * DD + j] = v;
}
__global__ void k_sethead(const int* __restrict__ h_index, const float* __restrict__ hs) {
    int id = threadIdx.x;  // BB*DD = 256 threads
    int b = id / DD, j = id % DD;
    int h = h_index[b];
    g_hidden[((size_t)b * NN + h) * DD + j] = hs[b * DD + j];
}

// rel_part[b] = rel @ W_bottom + linear_b
__global__ void k_relpart(const int* __restrict__ r_index, const float* __restrict__ rel_table,
                          const float* __restrict__ linear_w, const float* __restrict__ linear_b) {
    int b = blockIdx.x, j = threadIdx.x;  // 64 threads
    const float* rel = rel_table + (size_t)r_index[b] * DD;
    float acc = linear_b[j];
    for (int k = 0; k < DD; k++) acc += rel[k] * linear_w[(DD + k) * DD + j];
    g_relpart[b * DD + j] = acc;
}

// base = score_fn(0) = relu(b1) @ w2 + b2 (rel-independent)
__global__ void k_base(const float* __restrict__ mlp_b1, const float* __restrict__ mlp_w2,
                       const float* __restrict__ mlp_b2) {
    __shared__ float s[128];
    int t = threadIdx.x;
    s[t] = fmaxf(mlp_b1[t], 0.f) * mlp_w2[t];
    __syncthreads();
    for (int o = 64; o > 0; o >>= 1) {
        if (t < o) s[t] += s[t + o];
        __syncthreads();
    }
    if (t == 0) g_base = s[0] + mlp_b2[0];
}
__global__ void k_scorefill() {
    int i = blockIdx.x * blockDim.x + threadIdx.x;
    if (i < BB * NN) g_score[i] = g_base;
}

// initial head-only scoring (runs once; not perf-critical)
__global__ void __launch_bounds__(128) k_score_head(
        const int* __restrict__ h_index,
        const float* __restrict__ linear_w,
        const float* __restrict__ mlp_w1, const float* __restrict__ mlp_b1,
        const float* __restrict__ mlp_w2, const float* __restrict__ mlp_b2) {
    int b = blockIdx.y;
    int n = h_index[b];
    int t = threadIdx.x;  // 128
    __shared__ float sh[DD], sx[DD], sr[128];
    if (t < DD) sh[t] = g_hidden[((size_t)b * NN + n) * DD + t];
    __syncthreads();
    if (t < DD) {
        float acc = g_relpart[b * DD + t];
        #pragma unroll 8
        for (int k = 0; k < DD; k++) acc += sh[k] * linear_w[k * DD + t];
        sx[t] = sh[t] * acc;
    }
    __syncthreads();
    float h1 = mlp_b1[t];
    #pragma unroll 8
    for (int j = 0; j < DD; j++) h1 += sx[j] * mlp_w1[j * 128 + t];
    h1 = fmaxf(h1, 0.f);
    sr[t] = h1 * mlp_w2[t];
    __syncthreads();
    for (int o = 64; o > 0; o >>= 1) {
        if (t < o) sr[t] += sr[t + o];
        __syncthreads();
    }
    if (t == 0) g_score[b * NN + n] = sr[0] + mlp_b2[0];
}

// ---------------- single-kernel exact radix select (8-bit digits) ----------------
// One 1024-thread block per batch. Finds the exact k-th largest 64-bit key
// (keys are distinct: (ford(score)<<32) | (0x7FFFFFFF - index)), writes g_thresh[b].
// Nodes: keys generated on-the-fly from score. Edges: keys prebuilt in g_keyA.
__global__ void __launch_bounds__(1024) k_select(int isEdges) {
    int b = blockIdx.x;
    int t = threadIdx.x;
    int lane = t & 31;
    __shared__ int hist[256];
    __shared__ int sscan[256];
    __shared__ int s_bucket, s_k, s_pos;
    u64* bufA = g_keyA + (size_t)b * EE;
    u64* bufB = g_keyB + (size_t)b * EE;
    int cnt, k;
    if (isEdges) { cnt = g_cntA[b]; k = min(ESELC, cnt); }
    else         { cnt = NN;        k = KK; }
    if (cnt == 0) {  // no candidates: threshold above everything
        if (t == 0) g_thresh[b] = ~0ull;
        return;
    }
    const float* scoreb = g_score + b * NN;
    u64 thresh = 0;
    u64* src = bufA;
    u64* dst = bufB;
    bool materialized = isEdges;   // nodes start unmaterialized (generate from score)
    for (int pass = 0; pass < 8; pass++) {
        int shift = 56 - 8 * pass;
        __syncthreads();                 // everyone done reading hist from prev pass
        if (t < 256) hist[t] = 0;
        if (t == 0) s_pos = 0;
        __syncthreads();
        // histogram (warp-aggregated)
        for (int i = t; i < cnt; i += 1024) {
            u64 key = materialized ? src[i]
                : (((u64)ford(scoreb[i]) << 32) | (u32)(0x7FFFFFFF - i));
            int digit = (int)((key >> shift) & 255);
            u32 mk = __match_any_sync(__activemask(), digit);
            if ((mk & ((1u << lane) - 1)) == 0)
                atomicAdd(&hist[digit], __popc(mk));
        }
        __syncthreads();
        // suffix sums: sscan[d] = count of keys with digit >= d
        if (t < 256) sscan[t] = hist[t];
        __syncthreads();
        for (int off = 1; off < 256; off <<= 1) {
            int v = 0;
            if (t < 256 && t + off < 256) v = sscan[t + off];
            __syncthreads();
            if (t < 256) sscan[t] += v;
            __syncthreads();
        }
        if (t < 256) {
            int incl = sscan[t];
            int inxt = (t < 255) ? sscan[t + 1] : 0;
            if (incl >= k && inxt < k) { s_bucket = t; s_k = k - inxt; }
        }
        __syncthreads();
        int bucket = s_bucket;
        thresh |= ((u64)bucket) << shift;
        k = s_k;
        bool skip = (hist[bucket] == cnt);   // whole candidate set shares this digit
        if (!skip) {
            u64* out = materialized ? dst : bufA;
            for (int i = t; i < cnt; i += 1024) {
                u64 key = materialized ? src[i]
                    : (((u64)ford(scoreb[i]) << 32) | (u32)(0x7FFFFFFF - i));
                int digit = (int)((key >> shift) & 255);
                bool m = (digit == bucket);
                u32 am = __activemask();
                u32 bal = __ballot_sync(am, m);
                if (m) {
                    int leader = __ffs(bal) - 1;
                    int rank = __popc(bal & ((1u << lane) - 1));
                    int base = 0;
                    if (lane == leader) base = atomicAdd(&s_pos, __popc(bal));
                    base = __shfl_sync(bal, base, leader);
                    out[base + rank] = key;
                }
            }
            __syncthreads();
            cnt = s_pos;
            if (!materialized) { src = bufA; dst = bufB; materialized = true; }
            else               { u64* tmp = src; src = dst; dst = tmp; }
            if (cnt == 1) { thresh = src[0]; break; }  // unique candidate = k-th key
        }
    }
    if (t == 0) g_thresh[b] = thresh;
}

// build edge keys for selected-src edges (also counts them)
__global__ void k_selinit_edges() {
    int b = threadIdx.x;
    if (b < BB) { g_cntA[b] = 0; g_nsel[b] = 0; }
}
__global__ void k_ekeys(const int* __restrict__ esrc, const int* __restrict__ edst) {
    int b = blockIdx.y;
    int e = blockIdx.x * blockDim.x + threadIdx.x;
    if (e >= EE) return;
    if (!g_sel[b * NN + esrc[e]]) return;
    u64 key = ((u64)ford(g_score[b * NN + edst[e]]) << 32) | (u32)(0x7FFFFFFF - e);
    int p = atomicAdd(&g_cntA[b], 1);
    g_keyA[(size_t)b * EE + p] = key;
}
__global__ void k_marksel() {
    int b = blockIdx.y;
    int n = blockIdx.x * blockDim.x + threadIdx.x;
    if (n >= NN) return;
    u64 key = ((u64)ford(g_score[b * NN + n]) << 32) | (u32)(0x7FFFFFFF - n);
    g_sel[b * NN + n] = (key >= g_thresh[b]) ? 1 : 0;
}
__global__ void k_markedges(const int* __restrict__ esrc, const int* __restrict__ edst) {
    int b = blockIdx.y;
    int e = blockIdx.x * blockDim.x + threadIdx.x;
    if (e >= EE) return;
    if (!g_sel[b * NN + esrc[e]]) return;
    u64 key = ((u64)ford(g_score[b * NN + edst[e]]) << 32) | (u32)(0x7FFFFFFF - e);
    if (key >= g_thresh[b]) {
        int p = atomicAdd(&g_nsel[b], 1);
        if (p < ESELC) g_seledge[b * ESELC + p] = e;
    }
}

// ---------------- CSR build + gather aggregation ----------------
__global__ void k_clearcnt() {
    int i = blockIdx.x * blockDim.x + threadIdx.x;
    if (i < SCAN_N) g_cnt[i] = 0;
    if (i == 0) g_nact = 0;
}
__global__ void k_count(const int* __restrict__ edst) {
    int b = blockIdx.y;
    int i = blockIdx.x * blockDim.x + threadIdx.x;
    if (i >= g_nsel[b]) return;
    int e = g_seledge[b * ESELC + i];
    int idx = b * NN + edst[e];
    int old = atomicAdd(&g_cnt[idx], 1);
    if (old == 0) {
        int p = atomicAdd(&g_nact, 1);
        g_act[p] = idx;
    }
}
__global__ void __launch_bounds__(256) k_scan1() {
    __shared__ int s[256];
    int b = blockIdx.x, t = threadIdx.x;
    int i = b * 256 + t;
    int v = (i < SCAN_N) ? g_cnt[i] : 0;
    s[t] = v;
    __syncthreads();
    for (int off = 1; off < 256; off <<= 1) {
        int u = (t >= off) ? s[t - off] : 0;
        __syncthreads();
        s[t] += u;
        __syncthreads();
    }
    if (i < SCAN_N) g_off[i] = s[t];  // inclusive within block
    if (t == 255) g_bsum[b] = s[255];
}
__global__ void __launch_bounds__(1024) k_scan2() {
    __shared__ int s[1024];
    int t = threadIdx.x;
    int v = (t < SCAN_BLOCKS) ? g_bsum[t] : 0;
    s[t] = v;
    __syncthreads();
    for (int off = 1; off < 1024; off <<= 1) {
        int u = (t >= off) ? s[t - off] : 0;
        __syncthreads();
        s[t] += u;
        __syncthreads();
    }
    if (t < SCAN_BLOCKS) g_bsum[t] = s[t] - v;  // exclusive
}
__global__ void k_scan3() {
    int b = blockIdx.x, t = threadIdx.x;
    int i = b * 256 + t;
    if (i < SCAN_N) g_off[i] = g_off[i] - g_cnt[i] + g_bsum[b];  // exclusive start
}
__global__ void k_fill(const int* __restrict__ edst) {
    int b = blockIdx.y;
    int i = blockIdx.x * blockDim.x + threadIdx.x;
    if (i >= g_nsel[b]) return;
    int e = g_seledge[b * ESELC + i];
    int idx = b * NN + edst[e];
    int pos = atomicAdd(&g_off[idx], 1);   // g_off becomes end-offset
    g_csr[pos] = e;
}

// gather: one node per 64 threads, 4 nodes per block; registers-only aggregation
__global__ void __launch_bounds__(256) k_gather(
        const int* __restrict__ esrc, const int* __restrict__ etyp,
        const float* __restrict__ relw_l) {
    int t = threadIdx.x;
    int j = t & 63, slot = t >> 6;
    int nact = g_nact;
    int ngr = (nact + 3) >> 2;
    for (int g = blockIdx.x; g < ngr; g += gridDim.x) {
        int i = g * 4 + slot;
        if (i >= nact) continue;
        int idx = g_act[i];
        int b = idx / NN;
        int end = g_off[idx], cnt = g_cnt[idx], start = end - cnt;
        float sum = 0.f, sq = 0.f, mx = -INFINITY, mn = INFINITY;
        for (int k = start; k < end; k++) {
            int e = g_csr[k];
            int s = esrc[e], et = etyp[e];
            float gate = 1.f / (1.f + expf(-g_score[b * NN + s]));
            float m = gate * g_hidden[((size_t)b * NN + s) * DD + j]
                           * relw_l[(size_t)et * DD + j];
            sum += m; sq += m * m;
            mx = fmaxf(mx, m); mn = fminf(mn, m);
        }
        float degc = (float)cnt;  // cnt >= 1 for active nodes
        float mean = sum / degc;
        float stdv = sqrtf(fmaxf(sq / degc - mean * mean, 0.f) + 1e-6f);
        size_t o = (size_t)idx * DD + j;
        g_sumA[o] = mean; g_sqA[o] = stdv; g_mxA[o] = mx; g_mnA[o] = mn;
        if (j == 0) {
            float logd = logf(degc + 1.f);
            float dm = g_dmean;
            g_amp[idx] = logd / dm;
            g_att[idx] = dm / fmaxf(logd, 1e-6f);
        }
    }
}

// ---------------- PNA GEMM: 64-node tiles, 16 accumulators/thread ----------------
__global__ void __launch_bounds__(256) k_pnagemm(const float* __restrict__ pw,
                                                 const float* __restrict__ pb) {
    __shared__ float spw[4096];      // current pw chunk [j][o]
    __shared__ float sbase[4096];    // current agg base [nd][j] (broadcast reads)
    __shared__ float sscale[64 * 3];
    __shared__ int   sidx[64];
    __shared__ float spb[64];
    int t = threadIdx.x;
    if (t < 64) spb[t] = pb[t];
    int nact = g_nact;
    int ngroups = (nact + 63) >> 6;
    int oq = t & 15;     // 4 output cols: oq*4..oq*4+3
    int np = t >> 4;     // nodes np, np+16, np+32, np+48
    float4* spw4 = (float4*)spw;
    for (int g = blockIdx.x; g < ngroups; g += gridDim.x) {
        __syncthreads();  // previous group done with sidx/sscale/spw/sbase
        if (t < 64) {
            int i = g * 64 + t;
            int idx = (i < nact) ? g_act[i] : -1;
            sidx[t] = idx;
            if (idx >= 0) {
                sscale[t * 3 + 0] = 1.f;
                sscale[t * 3 + 1] = g_amp[idx];
                sscale[t * 3 + 2] = g_att[idx];
            } else {
                sscale[t * 3 + 0] = 0.f; sscale[t * 3 + 1] = 0.f; sscale[t * 3 + 2] = 0.f;
            }
        }
        __syncthreads();
        float4 acc[4];
        #pragma unroll
        for (int q = 0; q < 4; q++) acc[q] = make_float4(0.f, 0.f, 0.f, 0.f);
        for (int agg = 0; agg < 4; agg++) {
            const float* src = (agg == 0) ? g_sumA : (agg == 1) ? g_mxA
                              : (agg == 2) ? g_mnA : g_sqA;
            __syncthreads();  // previous compute done reading sbase
            #pragma unroll
            for (int q = 0; q < 16; q++) {
                int id = q * 256 + t;       // 4096 = 64 nodes x 64 dims
                int nd = id >> 6, jj = id & 63;
                int idx = sidx[nd];
                sbase[id] = (idx >= 0) ? src[(size_t)idx * 64 + jj] : 0.f;
            }
            for (int sc = 0; sc < 3; sc++) {
                __syncthreads();  // prev compute done reading spw; sbase fill visible
                const float4* pws = (const float4*)(pw + (size_t)(agg * 3 + sc) * 4096);
                #pragma unroll
                for (int q = 0; q < 4; q++) spw4[q * 256 + t] = pws[q * 256 + t];
                __syncthreads();
                float s0 = sscale[np * 3 + sc];
                float s1 = sscale[(np + 16) * 3 + sc];
                float s2 = sscale[(np + 32) * 3 + sc];
                float s3 = sscale[(np + 48) * 3 + sc];
                #pragma unroll 4
                for (int j = 0; j < 64; j++) {
                    float4 w = spw4[j * 16 + oq];
                    float a0 = sbase[np * 64 + j] * s0;
                    float a1 = sbase[(np + 16) * 64 + j] * s1;
                    float a2 = sbase[(np + 32) * 64 + j] * s2;
                    float a3 = sbase[(np + 48) * 64 + j] * s3;
                    acc[0].x += a0 * w.x; acc[0].y += a0 * w.y; acc[0].z += a0 * w.z; acc[0].w += a0 * w.w;
                    acc[1].x += a1 * w.x; acc[1].y += a1 * w.y; acc[1].z += a1 * w.z; acc[1].w += a1 * w.w;
                    acc[2].x += a2 * w.x; acc[2].y += a2 * w.y; acc[2].z += a2 * w.z; acc[2].w += a2 * w.w;
                    acc[3].x += a3 * w.x; acc[3].y += a3 * w.y; acc[3].z += a3 * w.z; acc[3].w += a3 * w.w;
                }
            }
        }
        int o = oq * 4;
        #pragma unroll
        for (int q = 0; q < 4; q++) {
            int idx = sidx[np + 16 * q];
            if (idx >= 0) {
                float* h = &g_hidden[(size_t)idx * 64 + o];
                h[0] += acc[q].x + spb[o];     h[1] += acc[q].y + spb[o + 1];
                h[2] += acc[q].z + spb[o + 2]; h[3] += acc[q].w + spb[o + 3];
            }
        }
    }
}

// ---------------- score MLP over active nodes, weights resident in smem ----------------
#define SC2_FLOATS 13824
#define SC2_BYTES  ((SC2_FLOATS + 8) * 4)
__global__ void __launch_bounds__(256) k_score2(
        const float* __restrict__ linw, const float* __restrict__ w1,
        const float* __restrict__ b1, const float* __restrict__ w2,
        const float* __restrict__ b2) {
    extern __shared__ float smx[];
    float* slin = smx;             // [k][o] 64x64
    float* sw1  = smx + 4096;      // [j][c] 64x128
    float* sw2  = smx + 12288;     // 128
    float* sb1  = smx + 12416;     // 128
    float* srp  = smx + 12544;     // 4x64
    float* sh   = smx + 12800;     // 8x64
    float* sx   = smx + 13312;     // 8x64
    int*  sidx  = (int*)(smx + 13824);  // 8
    int t = threadIdx.x;
    #pragma unroll
    for (int q = 0; q < 16; q++) slin[q * 256 + t] = linw[q * 256 + t];
    #pragma unroll
    for (int q = 0; q < 32; q++) sw1[q * 256 + t] = w1[q * 256 + t];
    if (t < 128) { sw2[t] = w2[t]; sb1[t] = b1[t]; }
    srp[t] = g_relpart[t];         // 256 = BB*64
    float b2v = b2[0];
    int nact = g_nact;
    int ngroups = (nact + 7) >> 3;
    int w = t >> 5, lane = t & 31;
    const float4* sw14 = (const float4*)sw1;
    for (int g = blockIdx.x; g < ngroups; g += gridDim.x) {
        __syncthreads();
        if (t < 8) { int i = g * 8 + t; sidx[t] = (i < nact) ? g_act[i] : -1; }
        __syncthreads();
        #pragma unroll
        for (int q = 0; q < 2; q++) {
            int id = q * 256 + t;
            int nd = id >> 6, jj = id & 63;
            int idx = sidx[nd];
            sh[id] = (idx >= 0) ? g_hidden[(size_t)idx * 64 + jj] : 0.f;
        }
        __syncthreads();
        // phase 1: x = h * (h @ linW_top + relpart)   (warp w owns node w)
        {
            int idx = sidx[w];
            int bb = (idx >= 0) ? idx / NN : 0;
            int o = lane * 2;
            float a0 = srp[bb * 64 + o], a1 = srp[bb * 64 + o + 1];
            const float* hrow = &sh[w * 64];
            #pragma unroll 8
            for (int k = 0; k < 64; k++) {
                float hk = hrow[k];
                a0 += hk * slin[k * 64 + o];
                a1 += hk * slin[k * 64 + o + 1];
            }
            sx[w * 64 + o]     = hrow[o]     * a0;
            sx[w * 64 + o + 1] = hrow[o + 1] * a1;
        }
        __syncthreads();
        // phase 2: score = relu(x @ w1 + b1) . w2 + b2
        {
            int idx = sidx[w];
            int c = lane * 4;
            float4 a = {sb1[c], sb1[c + 1], sb1[c + 2], sb1[c + 3]};
            const float* xrow = &sx[w * 64];
            #pragma unroll 8
            for (int j = 0; j < 64; j++) {
                float xj = xrow[j];
                float4 wv = sw14[j * 32 + lane];
                a.x += xj * wv.x; a.y += xj * wv.y;
                a.z += xj * wv.z; a.w += xj * wv.w;
            }
            float p = fmaxf(a.x, 0.f) * sw2[c]     + fmaxf(a.y, 0.f) * sw2[c + 1]
                    + fmaxf(a.z, 0.f) * sw2[c + 2] + fmaxf(a.w, 0.f) * sw2[c + 3];
            #pragma unroll
            for (int off = 16; off > 0; off >>= 1)
                p += __shfl_xor_sync(0xFFFFFFFFu, p, off);
            if (lane == 0 && idx >= 0) g_score[idx] = p + b2v;
        }
    }
}

__global__ void k_out(const int* __restrict__ t_index, float* __restrict__ out) {
    int i = blockIdx.x * blockDim.x + threadIdx.x;
    if (i >= BB * TT) return;
    int b = i / TT;
    out[i] = g_score[(size_t)b * NN + t_index[i]];
}

// ---------------- launch sequence ----------------
extern "C" void kernel_launch(void* const* d_in, const int* in_sizes, int n_in,
                              void* d_out, int out_size) {
    const int*   h_index         = (const int*)d_in[0];
    const int*   r_index         = (const int*)d_in[1];
    const int*   t_index         = (const int*)d_in[2];
    const int*   all_index       = (const int*)d_in[3];
    const int*   edge_src        = (const int*)d_in[4];
    const int*   edge_dst        = (const int*)d_in[5];
    const int*   edge_type       = (const int*)d_in[6];
    const float* hidden_states   = (const float*)d_in[7];
    const float* score_text_embs = (const float*)d_in[8];
    const float* rel_table       = (const float*)d_in[9];
    const float* linear_w        = (const float*)d_in[10];
    const float* linear_b        = (const float*)d_in[11];
    const float* mlp_w1          = (const float*)d_in[12];
    const float* mlp_b1          = (const float*)d_in[13];
    const float* mlp_w2          = (const float*)d_in[14];
    const float* mlp_b2          = (const float*)d_in[15];
    const float* relw            = (const float*)d_in[16];
    const float* pna_w           = (const float*)d_in[17];
    const float* pna_b           = (const float*)d_in[18];
    float* out = (float*)d_out;
    (void)in_sizes; (void)n_in; (void)out_size;

    cudaFuncSetAttribute(k_score2, cudaFuncAttributeMaxDynamicSharedMemorySize, SC2_BYTES);

    // ---- setup ----
    k_init0<<<cdiv((long long)BB * NN * DD, 256), 256>>>();
    k_degfull<<<cdiv(EE, 256), 256>>>(edge_src);
    k_dmean<<<cdiv(NN, 256), 256>>>();
    k_dmean_fin<<<1, 1>>>();
    k_owner<<<cdiv(MM, 256), 256>>>(all_index);
    k_scatter<<<cdiv((long long)MM * DD, 256), 256>>>(all_index, score_text_embs);
    k_sethead<<<1, BB * DD>>>(h_index, hidden_states);
    k_relpart<<<BB, DD>>>(r_index, rel_table, linear_w, linear_b);
    k_base<<<1, 128>>>(mlp_b1, mlp_w2, mlp_b2);
    k_scorefill<<<cdiv(BB * NN, 256), 256>>>();
    k_score_head<<<dim3(1, BB), 128>>>(h_index, linear_w, mlp_w1, mlp_b1, mlp_w2, mlp_b2);

    for (int l = 0; l < LL; l++) {
        const float* relw_l = relw + (size_t)l * R2C * DD;
        const float* pw     = pna_w + (size_t)l * 12 * DD * DD;
        const float* pb     = pna_b + (size_t)l * DD;

        // ---- node top-K (exact, tie-break lower index) ----
        k_select<<<BB, 1024>>>(0);
        k_marksel<<<dim3(cdiv(NN, 256), BB), 256>>>();

        // ---- edge top-ESEL among finite (sel-src) edges ----
        k_selinit_edges<<<1, 32>>>();
        k_ekeys<<<dim3(cdiv(EE, 256), BB), 256>>>(edge_src, edge_dst);
        k_select<<<BB, 1024>>>(1);
        k_markedges<<<dim3(cdiv(EE, 256), BB), 256>>>(edge_src, edge_dst);

        // ---- CSR build + gather aggregation ----
        k_clearcnt<<<SCAN_BLOCKS, 256>>>();
        k_count<<<dim3(cdiv(ESELC, 256), BB), 256>>>(edge_dst);
        k_scan1<<<SCAN_BLOCKS, 256>>>();
        k_scan2<<<1, 1024>>>();
        k_scan3<<<SCAN_BLOCKS, 256>>>();
        k_fill<<<dim3(cdiv(ESELC, 256), BB), 256>>>(edge_dst);
        k_gather<<<2048, 256>>>(edge_src, edge_type, relw_l);

        // ---- PNA update + rescore ----
        k_pnagemm<<<1184, 256>>>(pw, pb);
        k_score2<<<592, 256, SC2_BYTES>>>(linear_w, mlp_w1, mlp_b1, mlp_w2, mlp_b2);
    }

    k_out<<<cdiv(BB * TT, 128), 128>>>(t_index, out);
}